// round 10
// baseline (speedup 1.0000x reference)
#include <cuda_runtime.h>

#define BB    64
#define L1S   199
#define LL    200
#define NUMC  1000
#define DD    64
#define MM    50
#define DR    32          // d-range per scan block (d-split = 2)
#define CC    4           // time chunks
#define CT    50          // steps per chunk (LL/CC)
#define NBLK  (BB*CC*2)   // 512 phase blocks

// ---- scratch (static device globals; no allocation) ----
__device__ float  g_Wall[NUMC*64];     // softmax, padded to 64 (zeros 50..63)
__device__ float  g_Eall[2*NUMC*DD];   // sigmoid(vemb @ We + be)
__device__ float  g_Aall[2*NUMC*DD];   // tanh(vemb @ Wa + ba)
__device__ float  g_Kf  [NUMC*DD];     // kemb @ Wf[D:2D] + bf
__device__ float  g_read[BB*LL*DD];    // weighted read
__device__ float2 gA[NBLK*4*256];      // chunk affine scale  (per pair,thread)
__device__ float2 gB[NBLK*4*256];      // chunk affine offset

// ---- fast transcendentals ----
__device__ __forceinline__ float fast_sigmoid(float x) {
    return __fdividef(1.f, 1.f + __expf(-x));
}
__device__ __forceinline__ float fast_tanh(float x) {
    return 1.f - __fdividef(2.f, __expf(2.f * x) + 1.f);
}

// ---- packed f32x2 ops ----
#define FMA2(d, a, b, c) \
    asm("fma.rn.f32x2 %0, %1, %2, %3;" : "=l"(d) : "l"(a), "l"(b), "l"(c))
#define MUL2(d, a, b) \
    asm("mul.rn.f32x2 %0, %1, %2;" : "=l"(d) : "l"(a), "l"(b))
#define PACK2(d, lo, hi) \
    asm("mov.b64 %0, {%1, %2};" : "=l"(d) : "f"(lo), "f"(hi))
#define UNPACK2(lo, hi, s) \
    asm("mov.b64 {%0, %1}, %2;" : "=f"(lo), "=f"(hi) : "l"(s))

#define NEA 250
#define NWK 125

// ============================================================
// Kernel V: role-split vocab precompute (float4 staging).
// ============================================================
__global__ __launch_bounds__(256) void vocab_kernel(
    const float* __restrict__ kemb,  const float* __restrict__ vemb,
    const float* __restrict__ Mk,
    const float* __restrict__ We,    const float* __restrict__ be,
    const float* __restrict__ Wa,    const float* __restrict__ ba,
    const float* __restrict__ Wf,    const float* __restrict__ bf)
{
    extern __shared__ float sm[];
    const int tid = threadIdx.x;
    const int d   = tid & 63;
    const int pg  = tid >> 6;

    if (blockIdx.x < NEA) {
        float* sWe = sm;
        float* sWa = sWe + DD*DD;
        float* vs  = sWa + DD*DD;
        const int xbase = blockIdx.x * 8;

        #pragma unroll
        for (int j = tid; j < DD*DD/4; j += 256) {
            ((float4*)sWe)[j] = ((const float4*)We)[j];
            ((float4*)sWa)[j] = ((const float4*)Wa)[j];
        }
        #pragma unroll
        for (int j = tid; j < 8*DD/4; j += 256)
            ((float4*)vs)[j] = ((const float4*)(vemb + xbase*DD))[j];
        __syncthreads();

        const float bev = be[d], bav = ba[d];
        float ed0 = bev, ed1 = bev, ad0 = bav, ad1 = bav;
        const float* v0 = vs + (pg*2 + 0)*DD;
        const float* v1 = vs + (pg*2 + 1)*DD;
        #pragma unroll 8
        for (int i = 0; i < DD; i++) {
            const float we = sWe[i*DD + d];
            const float wa = sWa[i*DD + d];
            const float a0 = v0[i], a1 = v1[i];
            ed0 = fmaf(a0, we, ed0);  ad0 = fmaf(a0, wa, ad0);
            ed1 = fmaf(a1, we, ed1);  ad1 = fmaf(a1, wa, ad1);
        }
        int r0 = xbase + pg*2, r1 = r0 + 1;
        g_Eall[r0*DD + d] = fast_sigmoid(ed0);
        g_Aall[r0*DD + d] = fast_tanh(ad0);
        g_Eall[r1*DD + d] = fast_sigmoid(ed1);
        g_Aall[r1*DD + d] = fast_tanh(ad1);
    } else {
        float* sWf  = sm;
        float* sMkT = sWf + DD*DD;
        float* ks   = sMkT + DD*MM;
        float* part = ks + 8*DD;
        const int kbase = (blockIdx.x - NEA) * 8;

        #pragma unroll
        for (int j = tid; j < DD*DD/4; j += 256)
            ((float4*)sWf)[j] = ((const float4*)(Wf + DD*DD))[j];
        #pragma unroll
        for (int j = tid; j < MM*DD; j += 256) {
            int m = j >> 6, i = j & 63;
            sMkT[i*MM + m] = Mk[j];
        }
        #pragma unroll
        for (int j = tid; j < 8*DD/4; j += 256)
            ((float4*)ks)[j] = ((const float4*)(kemb + kbase*DD))[j];
        __syncthreads();

        const float bfv = bf[d];
        float kf0 = bfv, kf1 = bfv;
        float lg0 = 0.f, lg1 = 0.f;
        const int md = (d < MM) ? d : 0;
        const float* k0 = ks + (pg*2 + 0)*DD;
        const float* k1 = ks + (pg*2 + 1)*DD;
        #pragma unroll 8
        for (int i = 0; i < DD; i++) {
            const float wf = sWf[i*DD + d];
            const float mk = sMkT[i*MM + md];
            const float a0 = k0[i], a1 = k1[i];
            kf0 = fmaf(a0, wf, kf0);  lg0 = fmaf(a0, mk, lg0);
            kf1 = fmaf(a1, wf, kf1);  lg1 = fmaf(a1, mk, lg1);
        }
        g_Kf[(kbase + pg*2 + 0)*DD + d] = kf0;
        g_Kf[(kbase + pg*2 + 1)*DD + d] = kf1;

        float lgv0 = (d < MM) ? __expf(lg0) : 0.f;
        float lgv1 = (d < MM) ? __expf(lg1) : 0.f;
        float ps0 = lgv0, ps1 = lgv1;
        #pragma unroll
        for (int o = 16; o > 0; o >>= 1) {
            ps0 += __shfl_xor_sync(0xffffffffu, ps0, o);
            ps1 += __shfl_xor_sync(0xffffffffu, ps1, o);
        }
        if ((d & 31) == 0) {
            part[pg*4 + (d >> 5)]     = ps0;
            part[pg*4 + 2 + (d >> 5)] = ps1;
        }
        __syncthreads();
        // padded rows (stride 64): zeros for d >= 50
        g_Wall[(kbase + pg*2 + 0)*64 + d] =
            __fdividef(lgv0, part[pg*4] + part[pg*4 + 1]);
        g_Wall[(kbase + pg*2 + 1)*64 + d] =
            __fdividef(lgv1, part[pg*4 + 2] + part[pg*4 + 3]);
    }
}

// ---- shared staging helper for phase kernels (inlined) ----
// sw: CT*64 permuted padded w; sea: CT*64 interleaved (e,a) for DR d-lanes
__device__ __forceinline__ void stage_chunk(
    float* sw, float* sea, int* sq, int* sx,
    const int* cseqs, const int* rseqs, const int* shc, const int* shr,
    int b, int c, int dbase, int tid)
{
    if (tid < CT) {
        int t = c*CT + tid;
        int q  = (t == 0) ? cseqs[b*L1S] : shc[b*L1S + t - 1];
        int rr = (t == 0) ? rseqs[b*L1S] : shr[b*L1S + t - 1];
        sq[tid] = q;
        sx[tid] = q + NUMC * rr;
    }
    __syncthreads();

    // w: CT rows x 16 float4 (stride-64 padded rows), permuted scatter
    for (int j = tid; j < CT*16; j += 256) {
        int i = j >> 4, f4 = j & 15;
        float4 wv = *(const float4*)&g_Wall[sq[i]*64 + f4*4];
        const float* w = (const float*)&wv;
        #pragma unroll
        for (int k = 0; k < 4; k++) {
            int m = f4*4 + k;
            int idx = (m >> 4)*16 + ((m & 7) << 1) + ((m >> 3) & 1);
            sw[i*64 + idx] = w[k];
        }
    }
    // (e,a): CT rows x 8 float4 over the DR d-lanes, interleaved
    for (int j = tid; j < CT*8; j += 256) {
        int i = j >> 3, f4 = j & 7;
        int off = sx[i]*DD + dbase + f4*4;
        float4 ev = *(const float4*)&g_Eall[off];
        float4 av = *(const float4*)&g_Aall[off];
        const float* e = (const float*)&ev;
        const float* a = (const float*)&av;
        #pragma unroll
        for (int k = 0; k < 4; k++) {
            sea[i*64 + (f4*4 + k)*2 + 0] = e[k];
            sea[i*64 + (f4*4 + k)*2 + 1] = a[k];
        }
    }
    __syncthreads();
}

// ============================================================
// Phase 1: per-chunk affine composition (A,B). grid = 512.
// block = (b*CC + c)*2 + half, 256 threads (g=tid&7, dl=tid>>3).
// ============================================================
__global__ __launch_bounds__(256) void scan_phase1(
    const int* __restrict__ cseqs, const int* __restrict__ rseqs,
    const int* __restrict__ shc,   const int* __restrict__ shr)
{
    __shared__ float sw[CT*64];
    __shared__ float sea[CT*64];
    __shared__ int   sq[CT], sx[CT];

    const int bx    = blockIdx.x;
    const int b     = bx >> 3;
    const int c     = (bx >> 1) & 3;
    const int dbase = (bx & 1) * DR;
    const int tid   = threadIdx.x;

    stage_chunk(sw, sea, sq, sx, cseqs, rseqs, shc, shr, b, c, dbase, tid);

    const int g  = tid & 7;
    const int dl = tid >> 3;
    (void)g; (void)dl;

    const float f1 = 1.f, f0 = 0.f;
    unsigned long long onep, A[4], Bv[4];
    PACK2(onep, f1, f1);
    #pragma unroll
    for (int pi = 0; pi < 4; pi++) { A[pi] = onep; PACK2(Bv[pi], f0, f0); }

    const float2* swp  = (const float2*)sw;
    const float2* seap = (const float2*)sea;

    #pragma unroll 2
    for (int i = 0; i < CT; i++) {
        const float2 ea = seap[i*32 + (tid >> 3)];
        const float ne = -ea.x;
        unsigned long long nep, ap;
        PACK2(nep, ne, ne);
        PACK2(ap, ea.y, ea.y);
        #pragma unroll
        for (int pi = 0; pi < 4; pi++) {
            float2 w2 = swp[i*32 + pi*8 + (tid & 7)];
            unsigned long long wp, alpha, beta;
            PACK2(wp, w2.x, w2.y);
            FMA2(alpha, nep, wp, onep);      // alpha = 1 - e*w
            MUL2(beta, wp, ap);              // beta  = w*a
            MUL2(A[pi], A[pi], alpha);       // A *= alpha
            FMA2(Bv[pi], alpha, Bv[pi], beta); // B = alpha*B + beta
        }
    }

    #pragma unroll
    for (int pi = 0; pi < 4; pi++) {
        float lo, hi;
        UNPACK2(lo, hi, A[pi]);
        gA[(bx*4 + pi)*256 + tid] = make_float2(lo, hi);
        UNPACK2(lo, hi, Bv[pi]);
        gB[(bx*4 + pi)*256 + tid] = make_float2(lo, hi);
    }
}

// ============================================================
// Phase 3: compose chunk-start state, replay 50 steps, emit reads.
// grid = 512, 256 threads.
// ============================================================
__global__ __launch_bounds__(256) void scan_phase3(
    const int* __restrict__ cseqs, const int* __restrict__ rseqs,
    const int* __restrict__ shc,   const int* __restrict__ shr,
    const float* __restrict__ Mv0)
{
    __shared__ float sw[CT*64];
    __shared__ float sea[CT*64];
    __shared__ int   sq[CT], sx[CT];

    const int bx    = blockIdx.x;
    const int b     = bx >> 3;
    const int c     = (bx >> 1) & 3;
    const int dbase = (bx & 1) * DR;
    const int tid   = threadIdx.x;

    const int g  = tid & 7;
    const int dl = tid >> 3;

    // init mv from Mv0 (pads -> 0)
    unsigned long long mvp[4];
    #pragma unroll
    for (int pi = 0; pi < 4; pi++) {
        int m0 = g + 16*pi, m1 = m0 + 8;
        float v0 = (m0 < MM) ? Mv0[m0*DD + dbase + dl] : 0.f;
        float v1 = (m1 < MM) ? Mv0[m1*DD + dbase + dl] : 0.f;
        PACK2(mvp[pi], v0, v1);
    }
    // compose previous chunks' affine maps
    for (int cc = 0; cc < c; cc++) {
        int bxx = ((b*CC + cc)*2) + (bx & 1);
        #pragma unroll
        for (int pi = 0; pi < 4; pi++) {
            float2 Av = gA[(bxx*4 + pi)*256 + tid];
            float2 Bv = gB[(bxx*4 + pi)*256 + tid];
            unsigned long long Ap, Bp;
            PACK2(Ap, Av.x, Av.y);
            PACK2(Bp, Bv.x, Bv.y);
            FMA2(mvp[pi], Ap, mvp[pi], Bp);   // mv = A*mv + B
        }
    }

    stage_chunk(sw, sea, sq, sx, cseqs, rseqs, shc, shr, b, c, dbase, tid);

    float* outr = g_read + b*LL*DD + (c*CT)*DD + dbase + dl;
    const float fz = 0.f;
    const float2* swp  = (const float2*)sw;
    const float2* seap = (const float2*)sea;

    #pragma unroll 2
    for (int i = 0; i < CT; i++) {
        const float2 ea = seap[i*32 + dl];
        const float ne = -ea.x;
        unsigned long long nep, aap, prp;
        PACK2(nep, ne, ne);
        PACK2(aap, ea.y, ea.y);
        PACK2(prp, fz, fz);

        #pragma unroll
        for (int pi = 0; pi < 4; pi++) {
            float2 w2 = swp[i*32 + pi*8 + g];
            unsigned long long wp, tt;
            PACK2(wp, w2.x, w2.y);
            FMA2(prp, wp, mvp[pi], prp);     // read (before update)
            FMA2(tt, nep, mvp[pi], aap);     // a - e*mv
            FMA2(mvp[pi], wp, tt, mvp[pi]);  // mv += w*(a - e*mv)
        }
        float plo, phi;
        UNPACK2(plo, phi, prp);
        float pr = plo + phi;
        pr += __shfl_xor_sync(0xffffffffu, pr, 1);
        pr += __shfl_xor_sync(0xffffffffu, pr, 2);
        pr += __shfl_xor_sync(0xffffffffu, pr, 4);
        if (g == 0) outr[i*DD] = pr;
    }
}

// ============================================================
// Kernel C: output MLP. 32 positions/block, grid=400, block=256.
// ============================================================
__global__ __launch_bounds__(256) void output_kernel(
    const int*  __restrict__ cseqs, const int* __restrict__ shc,
    const float* __restrict__ Wf,   const float* __restrict__ Wp,
    const float* __restrict__ bp,   float* __restrict__ out)
{
    __shared__ float sW[DD*DD];
    __shared__ float rs[32][DD];

    const int tid   = threadIdx.x;
    const int lane  = tid & 31;
    const int warp  = tid >> 5;
    const int pbase = blockIdx.x * 32;

    #pragma unroll
    for (int j = tid; j < DD*DD/4; j += 256)
        ((float4*)sW)[j] = ((const float4*)Wf)[j];
    #pragma unroll
    for (int j = tid; j < 32*DD/4; j += 256)
        ((float4*)rs)[j] = ((const float4*)(g_read + pbase*DD))[j];
    __syncthreads();

    float acc0[4], acc1[4];
    int posq[4];
    #pragma unroll
    for (int jj = 0; jj < 4; jj++) {
        int pos = pbase + warp*4 + jj;
        int bb = pos / LL, t = pos - bb*LL;
        int q = (t == 0) ? cseqs[bb*L1S] : shc[bb*L1S + t - 1];
        posq[jj] = pos;
        acc0[jj] = g_Kf[q*DD + lane];
        acc1[jj] = g_Kf[q*DD + 32 + lane];
    }

    const float4* r0 = (const float4*)rs[warp*4 + 0];
    const float4* r1 = (const float4*)rs[warp*4 + 1];
    const float4* r2 = (const float4*)rs[warp*4 + 2];
    const float4* r3 = (const float4*)rs[warp*4 + 3];

    #pragma unroll
    for (int i4 = 0; i4 < DD/4; i4++) {
        float ra[4], rb[4], rc[4], rd[4];
        *(float4*)ra = r0[i4];
        *(float4*)rb = r1[i4];
        *(float4*)rc = r2[i4];
        *(float4*)rd = r3[i4];
        #pragma unroll
        for (int k = 0; k < 4; k++) {
            const float wv0 = sW[(4*i4 + k)*DD + lane];
            const float wv1 = sW[(4*i4 + k)*DD + 32 + lane];
            acc0[0] = fmaf(ra[k], wv0, acc0[0]);
            acc1[0] = fmaf(ra[k], wv1, acc1[0]);
            acc0[1] = fmaf(rb[k], wv0, acc0[1]);
            acc1[1] = fmaf(rb[k], wv1, acc1[1]);
            acc0[2] = fmaf(rc[k], wv0, acc0[2]);
            acc1[2] = fmaf(rc[k], wv1, acc1[2]);
            acc0[3] = fmaf(rd[k], wv0, acc0[3]);
            acc1[3] = fmaf(rd[k], wv1, acc1[3]);
        }
    }

    const float wp0 = Wp[lane];
    const float wp1 = Wp[32 + lane];
    const float bpv = bp[0];
    #pragma unroll
    for (int jj = 0; jj < 4; jj++) {
        float p = fast_tanh(acc0[jj]) * wp0 + fast_tanh(acc1[jj]) * wp1;
        #pragma unroll
        for (int o = 16; o > 0; o >>= 1)
            p += __shfl_xor_sync(0xffffffffu, p, o);
        if (lane == 0)
            out[posq[jj]] = fast_sigmoid(p + bpv);
    }
}

// ============================================================
extern "C" void kernel_launch(void* const* d_in, const int* in_sizes, int n_in,
                              void* d_out, int out_size)
{
    const int*   cseqs = (const int*)  d_in[0];
    const int*   rseqs = (const int*)  d_in[1];
    const int*   shc   = (const int*)  d_in[2];
    const int*   shr   = (const int*)  d_in[3];
    const float* kemb  = (const float*)d_in[4];
    const float* vemb  = (const float*)d_in[5];
    const float* Mk    = (const float*)d_in[6];
    const float* Mv0   = (const float*)d_in[7];
    const float* Wf    = (const float*)d_in[8];
    const float* bf    = (const float*)d_in[9];
    const float* We    = (const float*)d_in[10];
    const float* be    = (const float*)d_in[11];
    const float* Wa    = (const float*)d_in[12];
    const float* ba    = (const float*)d_in[13];
    const float* Wp    = (const float*)d_in[14];
    const float* bp    = (const float*)d_in[15];
    float* out = (float*)d_out;

    size_t vsm = (size_t)(2*DD*DD + 8*DD + 32) * sizeof(float);
    cudaFuncSetAttribute(vocab_kernel,
                         cudaFuncAttributeMaxDynamicSharedMemorySize, (int)vsm);
    vocab_kernel<<<NEA + NWK, 256, vsm>>>(kemb, vemb, Mk, We, be, Wa, ba, Wf, bf);

    scan_phase1<<<NBLK, 256>>>(cseqs, rseqs, shc, shr);
    scan_phase3<<<NBLK, 256>>>(cseqs, rseqs, shc, shr, Mv0);

    output_kernel<<<BB*LL/32, 256>>>(cseqs, shc, Wf, Wp, bp, out);
}

// round 11
// speedup vs baseline: 1.0059x; 1.0059x over previous
#include <cuda_runtime.h>

#define BB    64
#define L1S   199
#define LL    200
#define NUMC  1000
#define DD    64
#define MM    50
#define DR    32          // d-range per scan block (d-split = 2)
#define CC    4           // time chunks
#define CT    50          // steps per chunk (LL/CC)
#define NBLK  (BB*CC*2)   // 512 phase blocks

// ---- scratch (static device globals; no allocation) ----
__device__ float  g_Wall[NUMC*64];     // softmax, padded to 64 (zeros 50..63)
__device__ float  g_Eall[2*NUMC*DD];   // sigmoid(vemb @ We + be)
__device__ float  g_Aall[2*NUMC*DD];   // tanh(vemb @ Wa + ba)
__device__ float  g_Kf  [NUMC*DD];     // kemb @ Wf[D:2D] + bf
__device__ float  g_read[BB*LL*DD];    // weighted read
__device__ float2 gA[NBLK*4*256];      // chunk affine scale  (per pair,thread)
__device__ float2 gB[NBLK*4*256];      // chunk affine offset

// ---- fast transcendentals ----
__device__ __forceinline__ float fast_sigmoid(float x) {
    return __fdividef(1.f, 1.f + __expf(-x));
}
__device__ __forceinline__ float fast_tanh(float x) {
    return 1.f - __fdividef(2.f, __expf(2.f * x) + 1.f);
}

// ---- packed f32x2 ops ----
#define FMA2(d, a, b, c) \
    asm("fma.rn.f32x2 %0, %1, %2, %3;" : "=l"(d) : "l"(a), "l"(b), "l"(c))
#define MUL2(d, a, b) \
    asm("mul.rn.f32x2 %0, %1, %2;" : "=l"(d) : "l"(a), "l"(b))
#define PACK2(d, lo, hi) \
    asm("mov.b64 %0, {%1, %2};" : "=l"(d) : "f"(lo), "f"(hi))
#define UNPACK2(lo, hi, s) \
    asm("mov.b64 {%0, %1}, %2;" : "=f"(lo), "=f"(hi) : "l"(s))

#define NEA 250
#define NWK 125

// ============================================================
// Kernel V: role-split vocab precompute (float4 staging).
// ============================================================
__global__ __launch_bounds__(256) void vocab_kernel(
    const float* __restrict__ kemb,  const float* __restrict__ vemb,
    const float* __restrict__ Mk,
    const float* __restrict__ We,    const float* __restrict__ be,
    const float* __restrict__ Wa,    const float* __restrict__ ba,
    const float* __restrict__ Wf,    const float* __restrict__ bf)
{
    extern __shared__ float sm[];
    const int tid = threadIdx.x;
    const int d   = tid & 63;
    const int pg  = tid >> 6;

    if (blockIdx.x < NEA) {
        float* sWe = sm;
        float* sWa = sWe + DD*DD;
        float* vs  = sWa + DD*DD;
        const int xbase = blockIdx.x * 8;

        #pragma unroll
        for (int j = tid; j < DD*DD/4; j += 256) {
            ((float4*)sWe)[j] = ((const float4*)We)[j];
            ((float4*)sWa)[j] = ((const float4*)Wa)[j];
        }
        #pragma unroll
        for (int j = tid; j < 8*DD/4; j += 256)
            ((float4*)vs)[j] = ((const float4*)(vemb + xbase*DD))[j];
        __syncthreads();

        const float bev = be[d], bav = ba[d];
        float ed0 = bev, ed1 = bev, ad0 = bav, ad1 = bav;
        const float* v0 = vs + (pg*2 + 0)*DD;
        const float* v1 = vs + (pg*2 + 1)*DD;
        #pragma unroll 8
        for (int i = 0; i < DD; i++) {
            const float we = sWe[i*DD + d];
            const float wa = sWa[i*DD + d];
            const float a0 = v0[i], a1 = v1[i];
            ed0 = fmaf(a0, we, ed0);  ad0 = fmaf(a0, wa, ad0);
            ed1 = fmaf(a1, we, ed1);  ad1 = fmaf(a1, wa, ad1);
        }
        int r0 = xbase + pg*2, r1 = r0 + 1;
        g_Eall[r0*DD + d] = fast_sigmoid(ed0);
        g_Aall[r0*DD + d] = fast_tanh(ad0);
        g_Eall[r1*DD + d] = fast_sigmoid(ed1);
        g_Aall[r1*DD + d] = fast_tanh(ad1);
    } else {
        float* sWf  = sm;
        float* sMkT = sWf + DD*DD;
        float* ks   = sMkT + DD*MM;
        float* part = ks + 8*DD;
        const int kbase = (blockIdx.x - NEA) * 8;

        #pragma unroll
        for (int j = tid; j < DD*DD/4; j += 256)
            ((float4*)sWf)[j] = ((const float4*)(Wf + DD*DD))[j];
        #pragma unroll
        for (int j = tid; j < MM*DD; j += 256) {
            int m = j >> 6, i = j & 63;
            sMkT[i*MM + m] = Mk[j];
        }
        #pragma unroll
        for (int j = tid; j < 8*DD/4; j += 256)
            ((float4*)ks)[j] = ((const float4*)(kemb + kbase*DD))[j];
        __syncthreads();

        const float bfv = bf[d];
        float kf0 = bfv, kf1 = bfv;
        float lg0 = 0.f, lg1 = 0.f;
        const int md = (d < MM) ? d : 0;
        const float* k0 = ks + (pg*2 + 0)*DD;
        const float* k1 = ks + (pg*2 + 1)*DD;
        #pragma unroll 8
        for (int i = 0; i < DD; i++) {
            const float wf = sWf[i*DD + d];
            const float mk = sMkT[i*MM + md];
            const float a0 = k0[i], a1 = k1[i];
            kf0 = fmaf(a0, wf, kf0);  lg0 = fmaf(a0, mk, lg0);
            kf1 = fmaf(a1, wf, kf1);  lg1 = fmaf(a1, mk, lg1);
        }
        g_Kf[(kbase + pg*2 + 0)*DD + d] = kf0;
        g_Kf[(kbase + pg*2 + 1)*DD + d] = kf1;

        float lgv0 = (d < MM) ? __expf(lg0) : 0.f;
        float lgv1 = (d < MM) ? __expf(lg1) : 0.f;
        float ps0 = lgv0, ps1 = lgv1;
        #pragma unroll
        for (int o = 16; o > 0; o >>= 1) {
            ps0 += __shfl_xor_sync(0xffffffffu, ps0, o);
            ps1 += __shfl_xor_sync(0xffffffffu, ps1, o);
        }
        if ((d & 31) == 0) {
            part[pg*4 + (d >> 5)]     = ps0;
            part[pg*4 + 2 + (d >> 5)] = ps1;
        }
        __syncthreads();
        // padded rows (stride 64): zeros for d >= 50
        g_Wall[(kbase + pg*2 + 0)*64 + d] =
            __fdividef(lgv0, part[pg*4] + part[pg*4 + 1]);
        g_Wall[(kbase + pg*2 + 1)*64 + d] =
            __fdividef(lgv1, part[pg*4 + 2] + part[pg*4 + 3]);
    }
}

// ---- shared staging helper for phase kernels (inlined) ----
// sw: CT*64 permuted padded w; sea: CT*64 interleaved (e,a) for DR d-lanes
__device__ __forceinline__ void stage_chunk(
    float* sw, float* sea, int* sq, int* sx,
    const int* cseqs, const int* rseqs, const int* shc, const int* shr,
    int b, int c, int dbase, int tid)
{
    if (tid < CT) {
        int t = c*CT + tid;
        int q  = (t == 0) ? cseqs[b*L1S] : shc[b*L1S + t - 1];
        int rr = (t == 0) ? rseqs[b*L1S] : shr[b*L1S + t - 1];
        sq[tid] = q;
        sx[tid] = q + NUMC * rr;
    }
    __syncthreads();

    // w: CT rows x 16 float4 (stride-64 padded rows), permuted scatter
    for (int j = tid; j < CT*16; j += 256) {
        int i = j >> 4, f4 = j & 15;
        float4 wv = *(const float4*)&g_Wall[sq[i]*64 + f4*4];
        const float* w = (const float*)&wv;
        #pragma unroll
        for (int k = 0; k < 4; k++) {
            int m = f4*4 + k;
            int idx = (m >> 4)*16 + ((m & 7) << 1) + ((m >> 3) & 1);
            sw[i*64 + idx] = w[k];
        }
    }
    // (e,a): CT rows x 8 float4 over the DR d-lanes, interleaved
    for (int j = tid; j < CT*8; j += 256) {
        int i = j >> 3, f4 = j & 7;
        int off = sx[i]*DD + dbase + f4*4;
        float4 ev = *(const float4*)&g_Eall[off];
        float4 av = *(const float4*)&g_Aall[off];
        const float* e = (const float*)&ev;
        const float* a = (const float*)&av;
        #pragma unroll
        for (int k = 0; k < 4; k++) {
            sea[i*64 + (f4*4 + k)*2 + 0] = e[k];
            sea[i*64 + (f4*4 + k)*2 + 1] = a[k];
        }
    }
    __syncthreads();
}

// ============================================================
// Phase 1: per-chunk affine composition (A,B). grid = 512.
// block = (b*CC + c)*2 + half, 256 threads (g=tid&7, dl=tid>>3).
// ============================================================
__global__ __launch_bounds__(256) void scan_phase1(
    const int* __restrict__ cseqs, const int* __restrict__ rseqs,
    const int* __restrict__ shc,   const int* __restrict__ shr)
{
    __shared__ float sw[CT*64];
    __shared__ float sea[CT*64];
    __shared__ int   sq[CT], sx[CT];

    const int bx    = blockIdx.x;
    const int b     = bx >> 3;
    const int c     = (bx >> 1) & 3;
    const int dbase = (bx & 1) * DR;
    const int tid   = threadIdx.x;

    stage_chunk(sw, sea, sq, sx, cseqs, rseqs, shc, shr, b, c, dbase, tid);

    const int g  = tid & 7;
    const int dl = tid >> 3;
    (void)g; (void)dl;

    const float f1 = 1.f, f0 = 0.f;
    unsigned long long onep, A[4], Bv[4];
    PACK2(onep, f1, f1);
    #pragma unroll
    for (int pi = 0; pi < 4; pi++) { A[pi] = onep; PACK2(Bv[pi], f0, f0); }

    const float2* swp  = (const float2*)sw;
    const float2* seap = (const float2*)sea;

    #pragma unroll 2
    for (int i = 0; i < CT; i++) {
        const float2 ea = seap[i*32 + (tid >> 3)];
        const float ne = -ea.x;
        unsigned long long nep, ap;
        PACK2(nep, ne, ne);
        PACK2(ap, ea.y, ea.y);
        #pragma unroll
        for (int pi = 0; pi < 4; pi++) {
            float2 w2 = swp[i*32 + pi*8 + (tid & 7)];
            unsigned long long wp, alpha, beta;
            PACK2(wp, w2.x, w2.y);
            FMA2(alpha, nep, wp, onep);      // alpha = 1 - e*w
            MUL2(beta, wp, ap);              // beta  = w*a
            MUL2(A[pi], A[pi], alpha);       // A *= alpha
            FMA2(Bv[pi], alpha, Bv[pi], beta); // B = alpha*B + beta
        }
    }

    #pragma unroll
    for (int pi = 0; pi < 4; pi++) {
        float lo, hi;
        UNPACK2(lo, hi, A[pi]);
        gA[(bx*4 + pi)*256 + tid] = make_float2(lo, hi);
        UNPACK2(lo, hi, Bv[pi]);
        gB[(bx*4 + pi)*256 + tid] = make_float2(lo, hi);
    }
}

// ============================================================
// Phase 3: compose chunk-start state, replay 50 steps, emit reads.
// grid = 512, 256 threads.
// ============================================================
__global__ __launch_bounds__(256) void scan_phase3(
    const int* __restrict__ cseqs, const int* __restrict__ rseqs,
    const int* __restrict__ shc,   const int* __restrict__ shr,
    const float* __restrict__ Mv0)
{
    __shared__ float sw[CT*64];
    __shared__ float sea[CT*64];
    __shared__ int   sq[CT], sx[CT];

    const int bx    = blockIdx.x;
    const int b     = bx >> 3;
    const int c     = (bx >> 1) & 3;
    const int dbase = (bx & 1) * DR;
    const int tid   = threadIdx.x;

    const int g  = tid & 7;
    const int dl = tid >> 3;

    // init mv from Mv0 (pads -> 0)
    unsigned long long mvp[4];
    #pragma unroll
    for (int pi = 0; pi < 4; pi++) {
        int m0 = g + 16*pi, m1 = m0 + 8;
        float v0 = (m0 < MM) ? Mv0[m0*DD + dbase + dl] : 0.f;
        float v1 = (m1 < MM) ? Mv0[m1*DD + dbase + dl] : 0.f;
        PACK2(mvp[pi], v0, v1);
    }
    // compose previous chunks' affine maps
    for (int cc = 0; cc < c; cc++) {
        int bxx = ((b*CC + cc)*2) + (bx & 1);
        #pragma unroll
        for (int pi = 0; pi < 4; pi++) {
            float2 Av = gA[(bxx*4 + pi)*256 + tid];
            float2 Bv = gB[(bxx*4 + pi)*256 + tid];
            unsigned long long Ap, Bp;
            PACK2(Ap, Av.x, Av.y);
            PACK2(Bp, Bv.x, Bv.y);
            FMA2(mvp[pi], Ap, mvp[pi], Bp);   // mv = A*mv + B
        }
    }

    stage_chunk(sw, sea, sq, sx, cseqs, rseqs, shc, shr, b, c, dbase, tid);

    float* outr = g_read + b*LL*DD + (c*CT)*DD + dbase + dl;
    const float fz = 0.f;
    const float2* swp  = (const float2*)sw;
    const float2* seap = (const float2*)sea;

    #pragma unroll 2
    for (int i = 0; i < CT; i++) {
        const float2 ea = seap[i*32 + dl];
        const float ne = -ea.x;
        unsigned long long nep, aap, prp;
        PACK2(nep, ne, ne);
        PACK2(aap, ea.y, ea.y);
        PACK2(prp, fz, fz);

        #pragma unroll
        for (int pi = 0; pi < 4; pi++) {
            float2 w2 = swp[i*32 + pi*8 + g];
            unsigned long long wp, tt;
            PACK2(wp, w2.x, w2.y);
            FMA2(prp, wp, mvp[pi], prp);     // read (before update)
            FMA2(tt, nep, mvp[pi], aap);     // a - e*mv
            FMA2(mvp[pi], wp, tt, mvp[pi]);  // mv += w*(a - e*mv)
        }
        float plo, phi;
        UNPACK2(plo, phi, prp);
        float pr = plo + phi;
        pr += __shfl_xor_sync(0xffffffffu, pr, 1);
        pr += __shfl_xor_sync(0xffffffffu, pr, 2);
        pr += __shfl_xor_sync(0xffffffffu, pr, 4);
        if (g == 0) outr[i*DD] = pr;
    }
}

// ============================================================
// Kernel C: output MLP. 32 positions/block, grid=400, block=256.
// ============================================================
__global__ __launch_bounds__(256) void output_kernel(
    const int*  __restrict__ cseqs, const int* __restrict__ shc,
    const float* __restrict__ Wf,   const float* __restrict__ Wp,
    const float* __restrict__ bp,   float* __restrict__ out)
{
    __shared__ float sW[DD*DD];
    __shared__ float rs[32][DD];

    const int tid   = threadIdx.x;
    const int lane  = tid & 31;
    const int warp  = tid >> 5;
    const int pbase = blockIdx.x * 32;

    #pragma unroll
    for (int j = tid; j < DD*DD/4; j += 256)
        ((float4*)sW)[j] = ((const float4*)Wf)[j];
    #pragma unroll
    for (int j = tid; j < 32*DD/4; j += 256)
        ((float4*)rs)[j] = ((const float4*)(g_read + pbase*DD))[j];
    __syncthreads();

    float acc0[4], acc1[4];
    int posq[4];
    #pragma unroll
    for (int jj = 0; jj < 4; jj++) {
        int pos = pbase + warp*4 + jj;
        int bb = pos / LL, t = pos - bb*LL;
        int q = (t == 0) ? cseqs[bb*L1S] : shc[bb*L1S + t - 1];
        posq[jj] = pos;
        acc0[jj] = g_Kf[q*DD + lane];
        acc1[jj] = g_Kf[q*DD + 32 + lane];
    }

    const float4* r0 = (const float4*)rs[warp*4 + 0];
    const float4* r1 = (const float4*)rs[warp*4 + 1];
    const float4* r2 = (const float4*)rs[warp*4 + 2];
    const float4* r3 = (const float4*)rs[warp*4 + 3];

    #pragma unroll
    for (int i4 = 0; i4 < DD/4; i4++) {
        float ra[4], rb[4], rc[4], rd[4];
        *(float4*)ra = r0[i4];
        *(float4*)rb = r1[i4];
        *(float4*)rc = r2[i4];
        *(float4*)rd = r3[i4];
        #pragma unroll
        for (int k = 0; k < 4; k++) {
            const float wv0 = sW[(4*i4 + k)*DD + lane];
            const float wv1 = sW[(4*i4 + k)*DD + 32 + lane];
            acc0[0] = fmaf(ra[k], wv0, acc0[0]);
            acc1[0] = fmaf(ra[k], wv1, acc1[0]);
            acc0[1] = fmaf(rb[k], wv0, acc0[1]);
            acc1[1] = fmaf(rb[k], wv1, acc1[1]);
            acc0[2] = fmaf(rc[k], wv0, acc0[2]);
            acc1[2] = fmaf(rc[k], wv1, acc1[2]);
            acc0[3] = fmaf(rd[k], wv0, acc0[3]);
            acc1[3] = fmaf(rd[k], wv1, acc1[3]);
        }
    }

    const float wp0 = Wp[lane];
    const float wp1 = Wp[32 + lane];
    const float bpv = bp[0];
    #pragma unroll
    for (int jj = 0; jj < 4; jj++) {
        float p = fast_tanh(acc0[jj]) * wp0 + fast_tanh(acc1[jj]) * wp1;
        #pragma unroll
        for (int o = 16; o > 0; o >>= 1)
            p += __shfl_xor_sync(0xffffffffu, p, o);
        if (lane == 0)
            out[posq[jj]] = fast_sigmoid(p + bpv);
    }
}

// ============================================================
extern "C" void kernel_launch(void* const* d_in, const int* in_sizes, int n_in,
                              void* d_out, int out_size)
{
    const int*   cseqs = (const int*)  d_in[0];
    const int*   rseqs = (const int*)  d_in[1];
    const int*   shc   = (const int*)  d_in[2];
    const int*   shr   = (const int*)  d_in[3];
    const float* kemb  = (const float*)d_in[4];
    const float* vemb  = (const float*)d_in[5];
    const float* Mk    = (const float*)d_in[6];
    const float* Mv0   = (const float*)d_in[7];
    const float* Wf    = (const float*)d_in[8];
    const float* bf    = (const float*)d_in[9];
    const float* We    = (const float*)d_in[10];
    const float* be    = (const float*)d_in[11];
    const float* Wa    = (const float*)d_in[12];
    const float* ba    = (const float*)d_in[13];
    const float* Wp    = (const float*)d_in[14];
    const float* bp    = (const float*)d_in[15];
    float* out = (float*)d_out;

    size_t vsm = (size_t)(2*DD*DD + 8*DD + 32) * sizeof(float);
    cudaFuncSetAttribute(vocab_kernel,
                         cudaFuncAttributeMaxDynamicSharedMemorySize, (int)vsm);
    vocab_kernel<<<NEA + NWK, 256, vsm>>>(kemb, vemb, Mk, We, be, Wa, ba, Wf, bf);

    scan_phase1<<<NBLK, 256>>>(cseqs, rseqs, shc, shr);
    scan_phase3<<<NBLK, 256>>>(cseqs, rseqs, shc, shr, Mv0);

    output_kernel<<<BB*LL/32, 256>>>(cseqs, shc, Wf, Wp, bp, out);
}

// round 12
// speedup vs baseline: 1.1634x; 1.1566x over previous
#include <cuda_runtime.h>

#define BB    64
#define L1S   199
#define LL    200
#define NUMC  1000
#define DD    64
#define MM    50
#define DR    32          // d-range per scan block (d-split = 2)
#define CC    4           // time chunks
#define CT    50          // steps per chunk

// ---- scratch (static device globals; no allocation) ----
__device__ float  g_Wall[NUMC*64];     // softmax, padded to 64 (zeros 50..63)
__device__ float  g_Eall[2*NUMC*DD];
__device__ float  g_Aall[2*NUMC*DD];
__device__ float  g_Kf  [NUMC*DD];
__device__ float  g_read[BB*LL*DD];

// ---- fast transcendentals ----
__device__ __forceinline__ float fast_sigmoid(float x) {
    return __fdividef(1.f, 1.f + __expf(-x));
}
__device__ __forceinline__ float fast_tanh(float x) {
    return 1.f - __fdividef(2.f, __expf(2.f * x) + 1.f);
}

// ---- packed f32x2 ops ----
#define FMA2(d, a, b, c) \
    asm("fma.rn.f32x2 %0, %1, %2, %3;" : "=l"(d) : "l"(a), "l"(b), "l"(c))
#define MUL2(d, a, b) \
    asm("mul.rn.f32x2 %0, %1, %2;" : "=l"(d) : "l"(a), "l"(b))
#define PACK2(d, lo, hi) \
    asm("mov.b64 %0, {%1, %2};" : "=l"(d) : "f"(lo), "f"(hi))
#define UNPACK2(lo, hi, s) \
    asm("mov.b64 {%0, %1}, %2;" : "=f"(lo), "=f"(hi) : "l"(s))

#define NEA 125   // EA blocks (16 x-rows each)
#define NWK 125   // WK blocks (8 k-rows each)

// ============================================================
// Kernel V: role-split vocab precompute.
// ============================================================
__global__ __launch_bounds__(256) void vocab_kernel(
    const float* __restrict__ kemb,  const float* __restrict__ vemb,
    const float* __restrict__ Mk,
    const float* __restrict__ We,    const float* __restrict__ be,
    const float* __restrict__ Wa,    const float* __restrict__ ba,
    const float* __restrict__ Wf,    const float* __restrict__ bf)
{
    extern __shared__ float sm[];
    const int tid = threadIdx.x;
    const int d   = tid & 63;
    const int pg  = tid >> 6;

    if (blockIdx.x < NEA) {
        // -------- EA path: 16 x-rows / block --------
        float* sWe = sm;
        float* sWa = sWe + DD*DD;
        float* vs  = sWa + DD*DD;          // 16*64
        const int xbase = blockIdx.x * 16;

        #pragma unroll
        for (int j = tid; j < DD*DD/4; j += 256) {
            ((float4*)sWe)[j] = ((const float4*)We)[j];
            ((float4*)sWa)[j] = ((const float4*)Wa)[j];
        }
        #pragma unroll
        for (int j = tid; j < 16*DD/4; j += 256)
            ((float4*)vs)[j] = ((const float4*)(vemb + xbase*DD))[j];
        __syncthreads();

        const float bev = be[d], bav = ba[d];
        float ed[4] = {bev, bev, bev, bev};
        float ad[4] = {bav, bav, bav, bav};
        const float* v0 = vs + (pg*4 + 0)*DD;
        const float* v1 = vs + (pg*4 + 1)*DD;
        const float* v2 = vs + (pg*4 + 2)*DD;
        const float* v3 = vs + (pg*4 + 3)*DD;
        #pragma unroll 8
        for (int i = 0; i < DD; i++) {
            const float we = sWe[i*DD + d];
            const float wa = sWa[i*DD + d];
            const float a0 = v0[i], a1 = v1[i], a2 = v2[i], a3 = v3[i];
            ed[0] = fmaf(a0, we, ed[0]);  ad[0] = fmaf(a0, wa, ad[0]);
            ed[1] = fmaf(a1, we, ed[1]);  ad[1] = fmaf(a1, wa, ad[1]);
            ed[2] = fmaf(a2, we, ed[2]);  ad[2] = fmaf(a2, wa, ad[2]);
            ed[3] = fmaf(a3, we, ed[3]);  ad[3] = fmaf(a3, wa, ad[3]);
        }
        #pragma unroll
        for (int jj = 0; jj < 4; jj++) {
            int r = xbase + pg*4 + jj;
            g_Eall[r*DD + d] = fast_sigmoid(ed[jj]);
            g_Aall[r*DD + d] = fast_tanh(ad[jj]);
        }
    } else {
        // -------- WK path: 8 k-rows / block --------
        float* sWf  = sm;
        float* sMkT = sWf + DD*DD;
        float* ks   = sMkT + DD*MM;
        float* part = ks + 8*DD;
        const int kbase = (blockIdx.x - NEA) * 8;

        #pragma unroll
        for (int j = tid; j < DD*DD/4; j += 256)
            ((float4*)sWf)[j] = ((const float4*)(Wf + DD*DD))[j];
        #pragma unroll
        for (int j = tid; j < MM*DD; j += 256) {
            int m = j >> 6, i = j & 63;
            sMkT[i*MM + m] = Mk[j];
        }
        #pragma unroll
        for (int j = tid; j < 8*DD/4; j += 256)
            ((float4*)ks)[j] = ((const float4*)(kemb + kbase*DD))[j];
        __syncthreads();

        const float bfv = bf[d];
        float kf0 = bfv, kf1 = bfv;
        float lg0 = 0.f, lg1 = 0.f;
        const int md = (d < MM) ? d : 0;
        const float* k0 = ks + (pg*2 + 0)*DD;
        const float* k1 = ks + (pg*2 + 1)*DD;
        #pragma unroll 8
        for (int i = 0; i < DD; i++) {
            const float wf = sWf[i*DD + d];
            const float mk = sMkT[i*MM + md];
            const float a0 = k0[i], a1 = k1[i];
            kf0 = fmaf(a0, wf, kf0);  lg0 = fmaf(a0, mk, lg0);
            kf1 = fmaf(a1, wf, kf1);  lg1 = fmaf(a1, mk, lg1);
        }
        g_Kf[(kbase + pg*2 + 0)*DD + d] = kf0;
        g_Kf[(kbase + pg*2 + 1)*DD + d] = kf1;

        float lgv0 = (d < MM) ? __expf(lg0) : 0.f;
        float lgv1 = (d < MM) ? __expf(lg1) : 0.f;
        float ps0 = lgv0, ps1 = lgv1;
        #pragma unroll
        for (int o = 16; o > 0; o >>= 1) {
            ps0 += __shfl_xor_sync(0xffffffffu, ps0, o);
            ps1 += __shfl_xor_sync(0xffffffffu, ps1, o);
        }
        if ((d & 31) == 0) {
            part[pg*4 + (d >> 5)]     = ps0;
            part[pg*4 + 2 + (d >> 5)] = ps1;
        }
        __syncthreads();
        g_Wall[(kbase + pg*2 + 0)*64 + d] =
            __fdividef(lgv0, part[pg*4] + part[pg*4 + 1]);
        g_Wall[(kbase + pg*2 + 1)*64 + d] =
            __fdividef(lgv1, part[pg*4 + 2] + part[pg*4 + 3]);
    }
}

// ---- chunk staging (per-team, 256 threads, ttid in [0,256)) ----
__device__ __forceinline__ void stage_chunk(
    float* sw, float* sea, int* sq, int* sx,
    const int* cseqs, const int* rseqs, const int* shc, const int* shr,
    int b, int c, int dbase, int ttid)
{
    if (ttid < CT) {
        int t = c*CT + ttid;
        int q  = (t == 0) ? cseqs[b*L1S] : shc[b*L1S + t - 1];
        int rr = (t == 0) ? rseqs[b*L1S] : shr[b*L1S + t - 1];
        sq[ttid] = q;
        sx[ttid] = q + NUMC * rr;
    }
    __syncthreads();

    for (int j = ttid; j < CT*16; j += 256) {
        int i = j >> 4, f4 = j & 15;
        float4 wv = *(const float4*)&g_Wall[sq[i]*64 + f4*4];
        const float* w = (const float*)&wv;
        #pragma unroll
        for (int k = 0; k < 4; k++) {
            int m = f4*4 + k;
            int idx = (m >> 4)*16 + ((m & 7) << 1) + ((m >> 3) & 1);
            sw[i*64 + idx] = w[k];
        }
    }
    for (int j = ttid; j < CT*8; j += 256) {
        int i = j >> 3, f4 = j & 7;
        int off = sx[i]*DD + dbase + f4*4;
        float4 ev = *(const float4*)&g_Eall[off];
        float4 av = *(const float4*)&g_Aall[off];
        const float* e = (const float*)&ev;
        const float* a = (const float*)&av;
        #pragma unroll
        for (int k = 0; k < 4; k++) {
            sea[i*64 + (f4*4 + k)*2 + 0] = e[k];
            sea[i*64 + (f4*4 + k)*2 + 1] = a[k];
        }
    }
    __syncthreads();
}

// ---- read-emitting 50-step scan over one staged chunk ----
__device__ __forceinline__ void scan_reads(
    const float* sw, const float* sea, unsigned long long* mvp,
    float* outr, int g, int dl)
{
    const float fz = 0.f;
    const float2* swp  = (const float2*)sw;
    const float2* seap = (const float2*)sea;
    #pragma unroll 2
    for (int i = 0; i < CT; i++) {
        const float2 ea = seap[i*32 + dl];
        const float ne = -ea.x;
        unsigned long long nep, aap, prp;
        PACK2(nep, ne, ne);
        PACK2(aap, ea.y, ea.y);
        PACK2(prp, fz, fz);
        #pragma unroll
        for (int pi = 0; pi < 4; pi++) {
            float2 w2 = swp[i*32 + pi*8 + g];
            unsigned long long wp, tt;
            PACK2(wp, w2.x, w2.y);
            FMA2(prp, wp, mvp[pi], prp);
            FMA2(tt, nep, mvp[pi], aap);
            FMA2(mvp[pi], wp, tt, mvp[pi]);
        }
        float plo, phi;
        UNPACK2(plo, phi, prp);
        float pr = plo + phi;
        pr += __shfl_xor_sync(0xffffffffu, pr, 1);
        pr += __shfl_xor_sync(0xffffffffu, pr, 2);
        pr += __shfl_xor_sync(0xffffffffu, pr, 4);
        if (g == 0) outr[i*DD] = pr;
    }
}

// ============================================================
// Fused scan: grid = 128 (b, d-half), 1024 threads = 4 chunk-teams.
// Team 0: scan chunk 0 w/ reads, publish final state.
// Teams 1-3: compute (A,B); 1,2 publish. Sync. Teams 1-3 compose
// start state from smem and replay their chunk emitting reads.
// ============================================================
__global__ __launch_bounds__(1024) void scan_fused(
    const int* __restrict__ cseqs, const int* __restrict__ rseqs,
    const int* __restrict__ shc,   const int* __restrict__ shr,
    const float* __restrict__ Mv0)
{
    extern __shared__ float sm[];
    float*  sw   = sm;                       // 4 * CT*64 = 12800
    float*  sea  = sw + 4*CT*64;             // 12800
    float2* pubMv = (float2*)(sea + 4*CT*64);   // 1024
    float2* pubA1 = pubMv + 1024;
    float2* pubB1 = pubA1 + 1024;
    float2* pubA2 = pubB1 + 1024;
    float2* pubB2 = pubA2 + 1024;
    int*    sq   = (int*)(pubB2 + 1024);     // 4*CT
    int*    sx   = sq + 4*CT;

    const int b     = blockIdx.x >> 1;
    const int dbase = (blockIdx.x & 1) * DR;
    const int tid   = threadIdx.x;
    const int team  = tid >> 8;
    const int ttid  = tid & 255;
    const int g     = ttid & 7;
    const int dl    = ttid >> 3;

    float* swT  = sw  + team*CT*64;
    float* seaT = sea + team*CT*64;

    stage_chunk(swT, seaT, sq + team*CT, sx + team*CT,
                cseqs, rseqs, shc, shr, b, team, dbase, ttid);

    if (team == 0) {
        // ---- chunk 0: direct scan with reads ----
        unsigned long long mvp[4];
        #pragma unroll
        for (int pi = 0; pi < 4; pi++) {
            int m0 = g + 16*pi, m1 = m0 + 8;
            float v0 = (m0 < MM) ? Mv0[m0*DD + dbase + dl] : 0.f;
            float v1 = (m1 < MM) ? Mv0[m1*DD + dbase + dl] : 0.f;
            PACK2(mvp[pi], v0, v1);
        }
        float* outr = g_read + b*LL*DD + dbase + dl;
        scan_reads(swT, seaT, mvp, outr, g, dl);
        #pragma unroll
        for (int pi = 0; pi < 4; pi++) {
            float lo, hi;
            UNPACK2(lo, hi, mvp[pi]);
            pubMv[pi*256 + ttid] = make_float2(lo, hi);
        }
    } else {
        // ---- chunks 1-3: affine composition ----
        const float f1 = 1.f, f0 = 0.f;
        unsigned long long onep, A[4], Bv[4];
        PACK2(onep, f1, f1);
        #pragma unroll
        for (int pi = 0; pi < 4; pi++) { A[pi] = onep; PACK2(Bv[pi], f0, f0); }

        const float2* swp  = (const float2*)swT;
        const float2* seap = (const float2*)seaT;
        #pragma unroll 2
        for (int i = 0; i < CT; i++) {
            const float2 ea = seap[i*32 + dl];
            const float ne = -ea.x;
            unsigned long long nep, ap;
            PACK2(nep, ne, ne);
            PACK2(ap, ea.y, ea.y);
            #pragma unroll
            for (int pi = 0; pi < 4; pi++) {
                float2 w2 = swp[i*32 + pi*8 + g];
                unsigned long long wp, alpha, beta;
                PACK2(wp, w2.x, w2.y);
                FMA2(alpha, nep, wp, onep);
                MUL2(beta, wp, ap);
                MUL2(A[pi], A[pi], alpha);
                FMA2(Bv[pi], alpha, Bv[pi], beta);
            }
        }
        if (team == 1) {
            #pragma unroll
            for (int pi = 0; pi < 4; pi++) {
                float lo, hi;
                UNPACK2(lo, hi, A[pi]);
                pubA1[pi*256 + ttid] = make_float2(lo, hi);
                UNPACK2(lo, hi, Bv[pi]);
                pubB1[pi*256 + ttid] = make_float2(lo, hi);
            }
        } else if (team == 2) {
            #pragma unroll
            for (int pi = 0; pi < 4; pi++) {
                float lo, hi;
                UNPACK2(lo, hi, A[pi]);
                pubA2[pi*256 + ttid] = make_float2(lo, hi);
                UNPACK2(lo, hi, Bv[pi]);
                pubB2[pi*256 + ttid] = make_float2(lo, hi);
            }
        }
    }
    __syncthreads();

    if (team > 0) {
        unsigned long long mvp[4];
        #pragma unroll
        for (int pi = 0; pi < 4; pi++) {
            float2 v = pubMv[pi*256 + ttid];
            PACK2(mvp[pi], v.x, v.y);
        }
        if (team >= 2) {
            #pragma unroll
            for (int pi = 0; pi < 4; pi++) {
                float2 Av = pubA1[pi*256 + ttid];
                float2 Bv = pubB1[pi*256 + ttid];
                unsigned long long Ap, Bp;
                PACK2(Ap, Av.x, Av.y);
                PACK2(Bp, Bv.x, Bv.y);
                FMA2(mvp[pi], Ap, mvp[pi], Bp);
            }
        }
        if (team == 3) {
            #pragma unroll
            for (int pi = 0; pi < 4; pi++) {
                float2 Av = pubA2[pi*256 + ttid];
                float2 Bv = pubB2[pi*256 + ttid];
                unsigned long long Ap, Bp;
                PACK2(Ap, Av.x, Av.y);
                PACK2(Bp, Bv.x, Bv.y);
                FMA2(mvp[pi], Ap, mvp[pi], Bp);
            }
        }
        float* outr = g_read + b*LL*DD + team*CT*DD + dbase + dl;
        scan_reads(swT, seaT, mvp, outr, g, dl);
    }
}

// ============================================================
// Kernel C: output MLP. 64 positions/block, grid=200, block=256.
// Warp handles 8 positions; lane owns d-cols (lane, lane+32).
// ============================================================
__global__ __launch_bounds__(256) void output_kernel(
    const int*  __restrict__ cseqs, const int* __restrict__ shc,
    const float* __restrict__ Wf,   const float* __restrict__ Wp,
    const float* __restrict__ bp,   float* __restrict__ out)
{
    __shared__ float sW[DD*DD];
    __shared__ float rs[64][DD];

    const int tid   = threadIdx.x;
    const int lane  = tid & 31;
    const int warp  = tid >> 5;
    const int pbase = blockIdx.x * 64;

    #pragma unroll
    for (int j = tid; j < DD*DD/4; j += 256)
        ((float4*)sW)[j] = ((const float4*)Wf)[j];
    #pragma unroll
    for (int j = tid; j < 64*DD/4; j += 256)
        ((float4*)rs)[j] = ((const float4*)(g_read + pbase*DD))[j];
    __syncthreads();

    float acc0[8], acc1[8];
    int posq[8];
    #pragma unroll
    for (int jj = 0; jj < 8; jj++) {
        int pos = pbase + warp*8 + jj;
        int bb = pos / LL, t = pos - bb*LL;
        int q = (t == 0) ? cseqs[bb*L1S] : shc[bb*L1S + t - 1];
        posq[jj] = pos;
        acc0[jj] = g_Kf[q*DD + lane];
        acc1[jj] = g_Kf[q*DD + 32 + lane];
    }

    #pragma unroll
    for (int i4 = 0; i4 < DD/4; i4++) {
        float4 rv[8];
        #pragma unroll
        for (int jj = 0; jj < 8; jj++)
            rv[jj] = ((const float4*)rs[warp*8 + jj])[i4];
        #pragma unroll
        for (int k = 0; k < 4; k++) {
            const float wv0 = sW[(4*i4 + k)*DD + lane];
            const float wv1 = sW[(4*i4 + k)*DD + 32 + lane];
            #pragma unroll
            for (int jj = 0; jj < 8; jj++) {
                const float r = ((const float*)&rv[jj])[k];
                acc0[jj] = fmaf(r, wv0, acc0[jj]);
                acc1[jj] = fmaf(r, wv1, acc1[jj]);
            }
        }
    }

    const float wp0 = Wp[lane];
    const float wp1 = Wp[32 + lane];
    const float bpv = bp[0];
    #pragma unroll
    for (int jj = 0; jj < 8; jj++) {
        float p = fast_tanh(acc0[jj]) * wp0 + fast_tanh(acc1[jj]) * wp1;
        #pragma unroll
        for (int o = 16; o > 0; o >>= 1)
            p += __shfl_xor_sync(0xffffffffu, p, o);
        if (lane == 0)
            out[posq[jj]] = fast_sigmoid(p + bpv);
    }
}

// ============================================================
extern "C" void kernel_launch(void* const* d_in, const int* in_sizes, int n_in,
                              void* d_out, int out_size)
{
    const int*   cseqs = (const int*)  d_in[0];
    const int*   rseqs = (const int*)  d_in[1];
    const int*   shc   = (const int*)  d_in[2];
    const int*   shr   = (const int*)  d_in[3];
    const float* kemb  = (const float*)d_in[4];
    const float* vemb  = (const float*)d_in[5];
    const float* Mk    = (const float*)d_in[6];
    const float* Mv0   = (const float*)d_in[7];
    const float* Wf    = (const float*)d_in[8];
    const float* bf    = (const float*)d_in[9];
    const float* We    = (const float*)d_in[10];
    const float* be    = (const float*)d_in[11];
    const float* Wa    = (const float*)d_in[12];
    const float* ba    = (const float*)d_in[13];
    const float* Wp    = (const float*)d_in[14];
    const float* bp    = (const float*)d_in[15];
    float* out = (float*)d_out;

    size_t vsm = (size_t)(2*DD*DD + 16*DD + 32) * sizeof(float);
    cudaFuncSetAttribute(vocab_kernel,
                         cudaFuncAttributeMaxDynamicSharedMemorySize, (int)vsm);
    vocab_kernel<<<NEA + NWK, 256, vsm>>>(kemb, vemb, Mk, We, be, Wa, ba, Wf, bf);

    size_t ssm = (size_t)(8*CT*64 + 5*1024*2) * sizeof(float)
               + (size_t)(8*CT) * sizeof(int);
    cudaFuncSetAttribute(scan_fused,
                         cudaFuncAttributeMaxDynamicSharedMemorySize, (int)ssm);
    scan_fused<<<BB*2, 1024, ssm>>>(cseqs, rseqs, shc, shr, Mv0);

    output_kernel<<<BB*LL/64, 256>>>(cseqs, shc, Wf, Wp, bp, out);
}

// round 13
// speedup vs baseline: 1.1704x; 1.0060x over previous
#include <cuda_runtime.h>

#define BB    64
#define L1S   199
#define LL    200
#define NUMC  1000
#define DD    64
#define MM    50
#define DR    32          // d-range per scan block (d-split = 2)
#define CC    4           // time chunks
#define CT    50          // steps per chunk

// ---- scratch (static device globals; no allocation) ----
__device__ float  g_Wall[NUMC*64];     // softmax, padded to 64 (zeros 50..63)
__device__ float  g_Eall[2*NUMC*DD];
__device__ float  g_Aall[2*NUMC*DD];
__device__ float  g_Kf  [NUMC*DD];
__device__ float  g_read[BB*LL*DD];

// ---- fast transcendentals ----
__device__ __forceinline__ float fast_sigmoid(float x) {
    return __fdividef(1.f, 1.f + __expf(-x));
}
__device__ __forceinline__ float fast_tanh(float x) {
    return 1.f - __fdividef(2.f, __expf(2.f * x) + 1.f);
}

// ---- packed f32x2 ops ----
#define FMA2(d, a, b, c) \
    asm("fma.rn.f32x2 %0, %1, %2, %3;" : "=l"(d) : "l"(a), "l"(b), "l"(c))
#define MUL2(d, a, b) \
    asm("mul.rn.f32x2 %0, %1, %2;" : "=l"(d) : "l"(a), "l"(b))
#define PACK2(d, lo, hi) \
    asm("mov.b64 %0, {%1, %2};" : "=l"(d) : "f"(lo), "f"(hi))
#define UNPACK2(lo, hi, s) \
    asm("mov.b64 {%0, %1}, %2;" : "=f"(lo), "=f"(hi) : "l"(s))

#define NEA 125   // EA blocks (16 x-rows each)
#define NWK 125   // WK blocks (8 k-rows each)

// ============================================================
// Kernel V: role-split vocab precompute.
// ============================================================
__global__ __launch_bounds__(256) void vocab_kernel(
    const float* __restrict__ kemb,  const float* __restrict__ vemb,
    const float* __restrict__ Mk,
    const float* __restrict__ We,    const float* __restrict__ be,
    const float* __restrict__ Wa,    const float* __restrict__ ba,
    const float* __restrict__ Wf,    const float* __restrict__ bf)
{
    extern __shared__ float sm[];
    const int tid = threadIdx.x;
    const int d   = tid & 63;
    const int pg  = tid >> 6;

    if (blockIdx.x < NEA) {
        // -------- EA path: 16 x-rows / block --------
        float* sWe = sm;
        float* sWa = sWe + DD*DD;
        float* vs  = sWa + DD*DD;          // 16*64
        const int xbase = blockIdx.x * 16;

        #pragma unroll
        for (int j = tid; j < DD*DD/4; j += 256) {
            ((float4*)sWe)[j] = ((const float4*)We)[j];
            ((float4*)sWa)[j] = ((const float4*)Wa)[j];
        }
        #pragma unroll
        for (int j = tid; j < 16*DD/4; j += 256)
            ((float4*)vs)[j] = ((const float4*)(vemb + xbase*DD))[j];
        __syncthreads();

        const float bev = be[d], bav = ba[d];
        float ed[4] = {bev, bev, bev, bev};
        float ad[4] = {bav, bav, bav, bav};
        const float* v0 = vs + (pg*4 + 0)*DD;
        const float* v1 = vs + (pg*4 + 1)*DD;
        const float* v2 = vs + (pg*4 + 2)*DD;
        const float* v3 = vs + (pg*4 + 3)*DD;
        #pragma unroll 8
        for (int i = 0; i < DD; i++) {
            const float we = sWe[i*DD + d];
            const float wa = sWa[i*DD + d];
            const float a0 = v0[i], a1 = v1[i], a2 = v2[i], a3 = v3[i];
            ed[0] = fmaf(a0, we, ed[0]);  ad[0] = fmaf(a0, wa, ad[0]);
            ed[1] = fmaf(a1, we, ed[1]);  ad[1] = fmaf(a1, wa, ad[1]);
            ed[2] = fmaf(a2, we, ed[2]);  ad[2] = fmaf(a2, wa, ad[2]);
            ed[3] = fmaf(a3, we, ed[3]);  ad[3] = fmaf(a3, wa, ad[3]);
        }
        #pragma unroll
        for (int jj = 0; jj < 4; jj++) {
            int r = xbase + pg*4 + jj;
            g_Eall[r*DD + d] = fast_sigmoid(ed[jj]);
            g_Aall[r*DD + d] = fast_tanh(ad[jj]);
        }
    } else {
        // -------- WK path: 8 k-rows / block --------
        float* sWf  = sm;
        float* sMkT = sWf + DD*DD;
        float* ks   = sMkT + DD*MM;
        float* part = ks + 8*DD;
        const int kbase = (blockIdx.x - NEA) * 8;

        #pragma unroll
        for (int j = tid; j < DD*DD/4; j += 256)
            ((float4*)sWf)[j] = ((const float4*)(Wf + DD*DD))[j];
        #pragma unroll
        for (int j = tid; j < MM*DD; j += 256) {
            int m = j >> 6, i = j & 63;
            sMkT[i*MM + m] = Mk[j];
        }
        #pragma unroll
        for (int j = tid; j < 8*DD/4; j += 256)
            ((float4*)ks)[j] = ((const float4*)(kemb + kbase*DD))[j];
        __syncthreads();

        const float bfv = bf[d];
        float kf0 = bfv, kf1 = bfv;
        float lg0 = 0.f, lg1 = 0.f;
        const int md = (d < MM) ? d : 0;
        const float* k0 = ks + (pg*2 + 0)*DD;
        const float* k1 = ks + (pg*2 + 1)*DD;
        #pragma unroll 8
        for (int i = 0; i < DD; i++) {
            const float wf = sWf[i*DD + d];
            const float mk = sMkT[i*MM + md];
            const float a0 = k0[i], a1 = k1[i];
            kf0 = fmaf(a0, wf, kf0);  lg0 = fmaf(a0, mk, lg0);
            kf1 = fmaf(a1, wf, kf1);  lg1 = fmaf(a1, mk, lg1);
        }
        g_Kf[(kbase + pg*2 + 0)*DD + d] = kf0;
        g_Kf[(kbase + pg*2 + 1)*DD + d] = kf1;

        float lgv0 = (d < MM) ? __expf(lg0) : 0.f;
        float lgv1 = (d < MM) ? __expf(lg1) : 0.f;
        float ps0 = lgv0, ps1 = lgv1;
        #pragma unroll
        for (int o = 16; o > 0; o >>= 1) {
            ps0 += __shfl_xor_sync(0xffffffffu, ps0, o);
            ps1 += __shfl_xor_sync(0xffffffffu, ps1, o);
        }
        if ((d & 31) == 0) {
            part[pg*4 + (d >> 5)]     = ps0;
            part[pg*4 + 2 + (d >> 5)] = ps1;
        }
        __syncthreads();
        g_Wall[(kbase + pg*2 + 0)*64 + d] =
            __fdividef(lgv0, part[pg*4] + part[pg*4 + 1]);
        g_Wall[(kbase + pg*2 + 1)*64 + d] =
            __fdividef(lgv1, part[pg*4 + 2] + part[pg*4 + 3]);
    }
}

// ---- chunk staging (per-team, 256 threads, ttid in [0,256)) ----
__device__ __forceinline__ void stage_chunk(
    float* sw, float* sea, int* sq, int* sx,
    const int* cseqs, const int* rseqs, const int* shc, const int* shr,
    int b, int c, int dbase, int ttid)
{
    if (ttid < CT) {
        int t = c*CT + ttid;
        int q  = (t == 0) ? cseqs[b*L1S] : shc[b*L1S + t - 1];
        int rr = (t == 0) ? rseqs[b*L1S] : shr[b*L1S + t - 1];
        sq[ttid] = q;
        sx[ttid] = q + NUMC * rr;
    }
    __syncthreads();

    for (int j = ttid; j < CT*16; j += 256) {
        int i = j >> 4, f4 = j & 15;
        float4 wv = *(const float4*)&g_Wall[sq[i]*64 + f4*4];
        const float* w = (const float*)&wv;
        #pragma unroll
        for (int k = 0; k < 4; k++) {
            int m = f4*4 + k;
            int idx = (m >> 4)*16 + ((m & 7) << 1) + ((m >> 3) & 1);
            sw[i*64 + idx] = w[k];
        }
    }
    for (int j = ttid; j < CT*8; j += 256) {
        int i = j >> 3, f4 = j & 7;
        int off = sx[i]*DD + dbase + f4*4;
        float4 ev = *(const float4*)&g_Eall[off];
        float4 av = *(const float4*)&g_Aall[off];
        const float* e = (const float*)&ev;
        const float* a = (const float*)&av;
        #pragma unroll
        for (int k = 0; k < 4; k++) {
            sea[i*64 + (f4*4 + k)*2 + 0] = e[k];
            sea[i*64 + (f4*4 + k)*2 + 1] = a[k];
        }
    }
    __syncthreads();
}

// ---- read-emitting 50-step scan over one staged chunk ----
__device__ __forceinline__ void scan_reads(
    const float* sw, const float* sea, unsigned long long* mvp,
    float* outr, int g, int dl)
{
    const float fz = 0.f;
    const float2* swp  = (const float2*)sw;
    const float2* seap = (const float2*)sea;
    #pragma unroll 2
    for (int i = 0; i < CT; i++) {
        const float2 ea = seap[i*32 + dl];
        const float ne = -ea.x;
        unsigned long long nep, aap, prp;
        PACK2(nep, ne, ne);
        PACK2(aap, ea.y, ea.y);
        PACK2(prp, fz, fz);
        #pragma unroll
        for (int pi = 0; pi < 4; pi++) {
            float2 w2 = swp[i*32 + pi*8 + g];
            unsigned long long wp, tt;
            PACK2(wp, w2.x, w2.y);
            FMA2(prp, wp, mvp[pi], prp);
            FMA2(tt, nep, mvp[pi], aap);
            FMA2(mvp[pi], wp, tt, mvp[pi]);
        }
        float plo, phi;
        UNPACK2(plo, phi, prp);
        float pr = plo + phi;
        pr += __shfl_xor_sync(0xffffffffu, pr, 1);
        pr += __shfl_xor_sync(0xffffffffu, pr, 2);
        pr += __shfl_xor_sync(0xffffffffu, pr, 4);
        if (g == 0) outr[i*DD] = pr;
    }
}

// ============================================================
// Fused scan: grid = 128 (b, d-half), 1024 threads = 4 chunk-teams.
// Team 0: scan chunk 0 w/ reads, publish final state.
// Teams 1-3: compute (A,B); 1,2 publish. Sync. Teams 1-3 compose
// start state from smem and replay their chunk emitting reads.
// ============================================================
__global__ __launch_bounds__(1024) void scan_fused(
    const int* __restrict__ cseqs, const int* __restrict__ rseqs,
    const int* __restrict__ shc,   const int* __restrict__ shr,
    const float* __restrict__ Mv0)
{
    extern __shared__ float sm[];
    float*  sw   = sm;                       // 4 * CT*64 = 12800
    float*  sea  = sw + 4*CT*64;             // 12800
    float2* pubMv = (float2*)(sea + 4*CT*64);   // 1024
    float2* pubA1 = pubMv + 1024;
    float2* pubB1 = pubA1 + 1024;
    float2* pubA2 = pubB1 + 1024;
    float2* pubB2 = pubA2 + 1024;
    int*    sq   = (int*)(pubB2 + 1024);     // 4*CT
    int*    sx   = sq + 4*CT;

    const int b     = blockIdx.x >> 1;
    const int dbase = (blockIdx.x & 1) * DR;
    const int tid   = threadIdx.x;
    const int team  = tid >> 8;
    const int ttid  = tid & 255;
    const int g     = ttid & 7;
    const int dl    = ttid >> 3;

    float* swT  = sw  + team*CT*64;
    float* seaT = sea + team*CT*64;

    stage_chunk(swT, seaT, sq + team*CT, sx + team*CT,
                cseqs, rseqs, shc, shr, b, team, dbase, ttid);

    if (team == 0) {
        // ---- chunk 0: direct scan with reads ----
        unsigned long long mvp[4];
        #pragma unroll
        for (int pi = 0; pi < 4; pi++) {
            int m0 = g + 16*pi, m1 = m0 + 8;
            float v0 = (m0 < MM) ? Mv0[m0*DD + dbase + dl] : 0.f;
            float v1 = (m1 < MM) ? Mv0[m1*DD + dbase + dl] : 0.f;
            PACK2(mvp[pi], v0, v1);
        }
        float* outr = g_read + b*LL*DD + dbase + dl;
        scan_reads(swT, seaT, mvp, outr, g, dl);
        #pragma unroll
        for (int pi = 0; pi < 4; pi++) {
            float lo, hi;
            UNPACK2(lo, hi, mvp[pi]);
            pubMv[pi*256 + ttid] = make_float2(lo, hi);
        }
    } else {
        // ---- chunks 1-3: affine composition ----
        const float f1 = 1.f, f0 = 0.f;
        unsigned long long onep, A[4], Bv[4];
        PACK2(onep, f1, f1);
        #pragma unroll
        for (int pi = 0; pi < 4; pi++) { A[pi] = onep; PACK2(Bv[pi], f0, f0); }

        const float2* swp  = (const float2*)swT;
        const float2* seap = (const float2*)seaT;
        #pragma unroll 2
        for (int i = 0; i < CT; i++) {
            const float2 ea = seap[i*32 + dl];
            const float ne = -ea.x;
            unsigned long long nep, ap;
            PACK2(nep, ne, ne);
            PACK2(ap, ea.y, ea.y);
            #pragma unroll
            for (int pi = 0; pi < 4; pi++) {
                float2 w2 = swp[i*32 + pi*8 + g];
                unsigned long long wp, alpha, beta;
                PACK2(wp, w2.x, w2.y);
                FMA2(alpha, nep, wp, onep);
                MUL2(beta, wp, ap);
                MUL2(A[pi], A[pi], alpha);
                FMA2(Bv[pi], alpha, Bv[pi], beta);
            }
        }
        if (team == 1) {
            #pragma unroll
            for (int pi = 0; pi < 4; pi++) {
                float lo, hi;
                UNPACK2(lo, hi, A[pi]);
                pubA1[pi*256 + ttid] = make_float2(lo, hi);
                UNPACK2(lo, hi, Bv[pi]);
                pubB1[pi*256 + ttid] = make_float2(lo, hi);
            }
        } else if (team == 2) {
            #pragma unroll
            for (int pi = 0; pi < 4; pi++) {
                float lo, hi;
                UNPACK2(lo, hi, A[pi]);
                pubA2[pi*256 + ttid] = make_float2(lo, hi);
                UNPACK2(lo, hi, Bv[pi]);
                pubB2[pi*256 + ttid] = make_float2(lo, hi);
            }
        }
    }
    __syncthreads();

    if (team > 0) {
        unsigned long long mvp[4];
        #pragma unroll
        for (int pi = 0; pi < 4; pi++) {
            float2 v = pubMv[pi*256 + ttid];
            PACK2(mvp[pi], v.x, v.y);
        }
        if (team >= 2) {
            #pragma unroll
            for (int pi = 0; pi < 4; pi++) {
                float2 Av = pubA1[pi*256 + ttid];
                float2 Bv = pubB1[pi*256 + ttid];
                unsigned long long Ap, Bp;
                PACK2(Ap, Av.x, Av.y);
                PACK2(Bp, Bv.x, Bv.y);
                FMA2(mvp[pi], Ap, mvp[pi], Bp);
            }
        }
        if (team == 3) {
            #pragma unroll
            for (int pi = 0; pi < 4; pi++) {
                float2 Av = pubA2[pi*256 + ttid];
                float2 Bv = pubB2[pi*256 + ttid];
                unsigned long long Ap, Bp;
                PACK2(Ap, Av.x, Av.y);
                PACK2(Bp, Bv.x, Bv.y);
                FMA2(mvp[pi], Ap, mvp[pi], Bp);
            }
        }
        float* outr = g_read + b*LL*DD + team*CT*DD + dbase + dl;
        scan_reads(swT, seaT, mvp, outr, g, dl);
    }
}

// ============================================================
// Kernel C: output MLP. 64 positions/block, grid=200, block=256.
// Warp handles 8 positions; lane owns d-cols (lane, lane+32).
// ============================================================
__global__ __launch_bounds__(256) void output_kernel(
    const int*  __restrict__ cseqs, const int* __restrict__ shc,
    const float* __restrict__ Wf,   const float* __restrict__ Wp,
    const float* __restrict__ bp,   float* __restrict__ out)
{
    __shared__ float sW[DD*DD];
    __shared__ float rs[64][DD];

    const int tid   = threadIdx.x;
    const int lane  = tid & 31;
    const int warp  = tid >> 5;
    const int pbase = blockIdx.x * 64;

    #pragma unroll
    for (int j = tid; j < DD*DD/4; j += 256)
        ((float4*)sW)[j] = ((const float4*)Wf)[j];
    #pragma unroll
    for (int j = tid; j < 64*DD/4; j += 256)
        ((float4*)rs)[j] = ((const float4*)(g_read + pbase*DD))[j];
    __syncthreads();

    float acc0[8], acc1[8];
    int posq[8];
    #pragma unroll
    for (int jj = 0; jj < 8; jj++) {
        int pos = pbase + warp*8 + jj;
        int bb = pos / LL, t = pos - bb*LL;
        int q = (t == 0) ? cseqs[bb*L1S] : shc[bb*L1S + t - 1];
        posq[jj] = pos;
        acc0[jj] = g_Kf[q*DD + lane];
        acc1[jj] = g_Kf[q*DD + 32 + lane];
    }

    #pragma unroll
    for (int i4 = 0; i4 < DD/4; i4++) {
        float4 rv[8];
        #pragma unroll
        for (int jj = 0; jj < 8; jj++)
            rv[jj] = ((const float4*)rs[warp*8 + jj])[i4];
        #pragma unroll
        for (int k = 0; k < 4; k++) {
            const float wv0 = sW[(4*i4 + k)*DD + lane];
            const float wv1 = sW[(4*i4 + k)*DD + 32 + lane];
            #pragma unroll
            for (int jj = 0; jj < 8; jj++) {
                const float r = ((const float*)&rv[jj])[k];
                acc0[jj] = fmaf(r, wv0, acc0[jj]);
                acc1[jj] = fmaf(r, wv1, acc1[jj]);
            }
        }
    }

    const float wp0 = Wp[lane];
    const float wp1 = Wp[32 + lane];
    const float bpv = bp[0];
    #pragma unroll
    for (int jj = 0; jj < 8; jj++) {
        float p = fast_tanh(acc0[jj]) * wp0 + fast_tanh(acc1[jj]) * wp1;
        #pragma unroll
        for (int o = 16; o > 0; o >>= 1)
            p += __shfl_xor_sync(0xffffffffu, p, o);
        if (lane == 0)
            out[posq[jj]] = fast_sigmoid(p + bpv);
    }
}

// ============================================================
extern "C" void kernel_launch(void* const* d_in, const int* in_sizes, int n_in,
                              void* d_out, int out_size)
{
    const int*   cseqs = (const int*)  d_in[0];
    const int*   rseqs = (const int*)  d_in[1];
    const int*   shc   = (const int*)  d_in[2];
    const int*   shr   = (const int*)  d_in[3];
    const float* kemb  = (const float*)d_in[4];
    const float* vemb  = (const float*)d_in[5];
    const float* Mk    = (const float*)d_in[6];
    const float* Mv0   = (const float*)d_in[7];
    const float* Wf    = (const float*)d_in[8];
    const float* bf    = (const float*)d_in[9];
    const float* We    = (const float*)d_in[10];
    const float* be    = (const float*)d_in[11];
    const float* Wa    = (const float*)d_in[12];
    const float* ba    = (const float*)d_in[13];
    const float* Wp    = (const float*)d_in[14];
    const float* bp    = (const float*)d_in[15];
    float* out = (float*)d_out;

    size_t vsm = (size_t)(2*DD*DD + 16*DD + 32) * sizeof(float);
    cudaFuncSetAttribute(vocab_kernel,
                         cudaFuncAttributeMaxDynamicSharedMemorySize, (int)vsm);
    vocab_kernel<<<NEA + NWK, 256, vsm>>>(kemb, vemb, Mk, We, be, Wa, ba, Wf, bf);

    size_t ssm = (size_t)(8*CT*64 + 5*1024*2) * sizeof(float)
               + (size_t)(8*CT) * sizeof(int);
    cudaFuncSetAttribute(scan_fused,
                         cudaFuncAttributeMaxDynamicSharedMemorySize, (int)ssm);
    scan_fused<<<BB*2, 1024, ssm>>>(cseqs, rseqs, shc, shr, Mv0);

    output_kernel<<<BB*LL/64, 256>>>(cseqs, shc, Wf, Wp, bp, out);
}

// round 14
// speedup vs baseline: 1.1714x; 1.0009x over previous
#include <cuda_runtime.h>

#define BB    64
#define L1S   199
#define LL    200
#define NUMC  1000
#define DD    64
#define MM    50
#define DR    32          // d-range per scan block (d-split = 2)
#define CC    4           // time chunks
#define CT    50          // steps per chunk

// ---- scratch (static device globals; no allocation) ----
__device__ float  g_Wall[NUMC*64];     // softmax, padded to 64 (zeros 50..63)
__device__ float  g_Eall[2*NUMC*DD];
__device__ float  g_Aall[2*NUMC*DD];
__device__ float  g_Kf  [NUMC*DD];
__device__ float  g_read[BB*LL*DD];

// ---- fast transcendentals ----
__device__ __forceinline__ float fast_sigmoid(float x) {
    return __fdividef(1.f, 1.f + __expf(-x));
}
__device__ __forceinline__ float fast_tanh(float x) {
    return 1.f - __fdividef(2.f, __expf(2.f * x) + 1.f);
}

// ---- packed f32x2 ops ----
#define FMA2(d, a, b, c) \
    asm("fma.rn.f32x2 %0, %1, %2, %3;" : "=l"(d) : "l"(a), "l"(b), "l"(c))
#define MUL2(d, a, b) \
    asm("mul.rn.f32x2 %0, %1, %2;" : "=l"(d) : "l"(a), "l"(b))
#define PACK2(d, lo, hi) \
    asm("mov.b64 %0, {%1, %2};" : "=l"(d) : "f"(lo), "f"(hi))
#define UNPACK2(lo, hi, s) \
    asm("mov.b64 {%0, %1}, %2;" : "=f"(lo), "=f"(hi) : "l"(s))

#define NEA 125   // EA blocks (16 x-rows each)
#define NWK 125   // WK blocks (8 k-rows each)

// ============================================================
// Kernel V: role-split vocab precompute.
// ============================================================
__global__ __launch_bounds__(256) void vocab_kernel(
    const float* __restrict__ kemb,  const float* __restrict__ vemb,
    const float* __restrict__ Mk,
    const float* __restrict__ We,    const float* __restrict__ be,
    const float* __restrict__ Wa,    const float* __restrict__ ba,
    const float* __restrict__ Wf,    const float* __restrict__ bf)
{
    extern __shared__ float sm[];
    const int tid = threadIdx.x;
    const int d   = tid & 63;
    const int pg  = tid >> 6;

    if (blockIdx.x < NEA) {
        // -------- EA path: 16 x-rows / block --------
        float* sWe = sm;
        float* sWa = sWe + DD*DD;
        float* vs  = sWa + DD*DD;          // 16*64
        const int xbase = blockIdx.x * 16;

        #pragma unroll
        for (int j = tid; j < DD*DD/4; j += 256) {
            ((float4*)sWe)[j] = ((const float4*)We)[j];
            ((float4*)sWa)[j] = ((const float4*)Wa)[j];
        }
        #pragma unroll
        for (int j = tid; j < 16*DD/4; j += 256)
            ((float4*)vs)[j] = ((const float4*)(vemb + xbase*DD))[j];
        __syncthreads();

        const float bev = be[d], bav = ba[d];
        float ed[4] = {bev, bev, bev, bev};
        float ad[4] = {bav, bav, bav, bav};
        const float* v0 = vs + (pg*4 + 0)*DD;
        const float* v1 = vs + (pg*4 + 1)*DD;
        const float* v2 = vs + (pg*4 + 2)*DD;
        const float* v3 = vs + (pg*4 + 3)*DD;
        #pragma unroll 8
        for (int i = 0; i < DD; i++) {
            const float we = sWe[i*DD + d];
            const float wa = sWa[i*DD + d];
            const float a0 = v0[i], a1 = v1[i], a2 = v2[i], a3 = v3[i];
            ed[0] = fmaf(a0, we, ed[0]);  ad[0] = fmaf(a0, wa, ad[0]);
            ed[1] = fmaf(a1, we, ed[1]);  ad[1] = fmaf(a1, wa, ad[1]);
            ed[2] = fmaf(a2, we, ed[2]);  ad[2] = fmaf(a2, wa, ad[2]);
            ed[3] = fmaf(a3, we, ed[3]);  ad[3] = fmaf(a3, wa, ad[3]);
        }
        #pragma unroll
        for (int jj = 0; jj < 4; jj++) {
            int r = xbase + pg*4 + jj;
            g_Eall[r*DD + d] = fast_sigmoid(ed[jj]);
            g_Aall[r*DD + d] = fast_tanh(ad[jj]);
        }
    } else {
        // -------- WK path: 8 k-rows / block --------
        float* sWf  = sm;
        float* sMkT = sWf + DD*DD;
        float* ks   = sMkT + DD*MM;
        float* part = ks + 8*DD;
        const int kbase = (blockIdx.x - NEA) * 8;

        #pragma unroll
        for (int j = tid; j < DD*DD/4; j += 256)
            ((float4*)sWf)[j] = ((const float4*)(Wf + DD*DD))[j];
        #pragma unroll
        for (int j = tid; j < MM*DD; j += 256) {
            int m = j >> 6, i = j & 63;
            sMkT[i*MM + m] = Mk[j];
        }
        #pragma unroll
        for (int j = tid; j < 8*DD/4; j += 256)
            ((float4*)ks)[j] = ((const float4*)(kemb + kbase*DD))[j];
        __syncthreads();

        const float bfv = bf[d];
        float kf0 = bfv, kf1 = bfv;
        float lg0 = 0.f, lg1 = 0.f;
        const int md = (d < MM) ? d : 0;
        const float* k0 = ks + (pg*2 + 0)*DD;
        const float* k1 = ks + (pg*2 + 1)*DD;
        #pragma unroll 8
        for (int i = 0; i < DD; i++) {
            const float wf = sWf[i*DD + d];
            const float mk = sMkT[i*MM + md];
            const float a0 = k0[i], a1 = k1[i];
            kf0 = fmaf(a0, wf, kf0);  lg0 = fmaf(a0, mk, lg0);
            kf1 = fmaf(a1, wf, kf1);  lg1 = fmaf(a1, mk, lg1);
        }
        g_Kf[(kbase + pg*2 + 0)*DD + d] = kf0;
        g_Kf[(kbase + pg*2 + 1)*DD + d] = kf1;

        float lgv0 = (d < MM) ? __expf(lg0) : 0.f;
        float lgv1 = (d < MM) ? __expf(lg1) : 0.f;
        float ps0 = lgv0, ps1 = lgv1;
        #pragma unroll
        for (int o = 16; o > 0; o >>= 1) {
            ps0 += __shfl_xor_sync(0xffffffffu, ps0, o);
            ps1 += __shfl_xor_sync(0xffffffffu, ps1, o);
        }
        if ((d & 31) == 0) {
            part[pg*4 + (d >> 5)]     = ps0;
            part[pg*4 + 2 + (d >> 5)] = ps1;
        }
        __syncthreads();
        g_Wall[(kbase + pg*2 + 0)*64 + d] =
            __fdividef(lgv0, part[pg*4] + part[pg*4 + 1]);
        g_Wall[(kbase + pg*2 + 1)*64 + d] =
            __fdividef(lgv1, part[pg*4 + 2] + part[pg*4 + 3]);
    }
}

// ---- chunk staging (per-team, 256 threads, ttid in [0,256)) ----
__device__ __forceinline__ void stage_chunk(
    float* sw, float* sea, int* sq, int* sx,
    const int* cseqs, const int* rseqs, const int* shc, const int* shr,
    int b, int c, int dbase, int ttid)
{
    if (ttid < CT) {
        int t = c*CT + ttid;
        int q  = (t == 0) ? cseqs[b*L1S] : shc[b*L1S + t - 1];
        int rr = (t == 0) ? rseqs[b*L1S] : shr[b*L1S + t - 1];
        sq[ttid] = q;
        sx[ttid] = q + NUMC * rr;
    }
    __syncthreads();

    for (int j = ttid; j < CT*16; j += 256) {
        int i = j >> 4, f4 = j & 15;
        float4 wv = *(const float4*)&g_Wall[sq[i]*64 + f4*4];
        const float* w = (const float*)&wv;
        #pragma unroll
        for (int k = 0; k < 4; k++) {
            int m = f4*4 + k;
            int idx = (m >> 4)*16 + ((m & 7) << 1) + ((m >> 3) & 1);
            sw[i*64 + idx] = w[k];
        }
    }
    for (int j = ttid; j < CT*8; j += 256) {
        int i = j >> 3, f4 = j & 7;
        int off = sx[i]*DD + dbase + f4*4;
        float4 ev = *(const float4*)&g_Eall[off];
        float4 av = *(const float4*)&g_Aall[off];
        const float* e = (const float*)&ev;
        const float* a = (const float*)&av;
        #pragma unroll
        for (int k = 0; k < 4; k++) {
            sea[i*64 + (f4*4 + k)*2 + 0] = e[k];
            sea[i*64 + (f4*4 + k)*2 + 1] = a[k];
        }
    }
    __syncthreads();
}

// ---- read-emitting 50-step scan over one staged chunk ----
__device__ __forceinline__ void scan_reads(
    const float* sw, const float* sea, unsigned long long* mvp,
    float* outr, int g, int dl)
{
    const float fz = 0.f;
    const float2* swp  = (const float2*)sw;
    const float2* seap = (const float2*)sea;
    #pragma unroll 2
    for (int i = 0; i < CT; i++) {
        const float2 ea = seap[i*32 + dl];
        const float ne = -ea.x;
        unsigned long long nep, aap, prp;
        PACK2(nep, ne, ne);
        PACK2(aap, ea.y, ea.y);
        PACK2(prp, fz, fz);
        #pragma unroll
        for (int pi = 0; pi < 4; pi++) {
            float2 w2 = swp[i*32 + pi*8 + g];
            unsigned long long wp, tt;
            PACK2(wp, w2.x, w2.y);
            FMA2(prp, wp, mvp[pi], prp);
            FMA2(tt, nep, mvp[pi], aap);
            FMA2(mvp[pi], wp, tt, mvp[pi]);
        }
        float plo, phi;
        UNPACK2(plo, phi, prp);
        float pr = plo + phi;
        pr += __shfl_xor_sync(0xffffffffu, pr, 1);
        pr += __shfl_xor_sync(0xffffffffu, pr, 2);
        pr += __shfl_xor_sync(0xffffffffu, pr, 4);
        if (g == 0) outr[i*DD] = pr;
    }
}

// ============================================================
// Fused scan: grid = 128 (b, d-half), 1024 threads = 4 chunk-teams.
// Team 0: scan chunk 0 w/ reads, publish final state.
// Teams 1-3: compute (A,B); 1,2 publish. Sync. Teams 1-3 compose
// start state from smem and replay their chunk emitting reads.
// ============================================================
__global__ __launch_bounds__(1024) void scan_fused(
    const int* __restrict__ cseqs, const int* __restrict__ rseqs,
    const int* __restrict__ shc,   const int* __restrict__ shr,
    const float* __restrict__ Mv0)
{
    extern __shared__ float sm[];
    float*  sw   = sm;                       // 4 * CT*64 = 12800
    float*  sea  = sw + 4*CT*64;             // 12800
    float2* pubMv = (float2*)(sea + 4*CT*64);   // 1024
    float2* pubA1 = pubMv + 1024;
    float2* pubB1 = pubA1 + 1024;
    float2* pubA2 = pubB1 + 1024;
    float2* pubB2 = pubA2 + 1024;
    int*    sq   = (int*)(pubB2 + 1024);     // 4*CT
    int*    sx   = sq + 4*CT;

    const int b     = blockIdx.x >> 1;
    const int dbase = (blockIdx.x & 1) * DR;
    const int tid   = threadIdx.x;
    const int team  = tid >> 8;
    const int ttid  = tid & 255;
    const int g     = ttid & 7;
    const int dl    = ttid >> 3;

    float* swT  = sw  + team*CT*64;
    float* seaT = sea + team*CT*64;

    stage_chunk(swT, seaT, sq + team*CT, sx + team*CT,
                cseqs, rseqs, shc, shr, b, team, dbase, ttid);

    if (team == 0) {
        // ---- chunk 0: direct scan with reads ----
        unsigned long long mvp[4];
        #pragma unroll
        for (int pi = 0; pi < 4; pi++) {
            int m0 = g + 16*pi, m1 = m0 + 8;
            float v0 = (m0 < MM) ? Mv0[m0*DD + dbase + dl] : 0.f;
            float v1 = (m1 < MM) ? Mv0[m1*DD + dbase + dl] : 0.f;
            PACK2(mvp[pi], v0, v1);
        }
        float* outr = g_read + b*LL*DD + dbase + dl;
        scan_reads(swT, seaT, mvp, outr, g, dl);
        #pragma unroll
        for (int pi = 0; pi < 4; pi++) {
            float lo, hi;
            UNPACK2(lo, hi, mvp[pi]);
            pubMv[pi*256 + ttid] = make_float2(lo, hi);
        }
    } else {
        // ---- chunks 1-3: affine composition ----
        const float f1 = 1.f, f0 = 0.f;
        unsigned long long onep, A[4], Bv[4];
        PACK2(onep, f1, f1);
        #pragma unroll
        for (int pi = 0; pi < 4; pi++) { A[pi] = onep; PACK2(Bv[pi], f0, f0); }

        const float2* swp  = (const float2*)swT;
        const float2* seap = (const float2*)seaT;
        #pragma unroll 2
        for (int i = 0; i < CT; i++) {
            const float2 ea = seap[i*32 + dl];
            const float ne = -ea.x;
            unsigned long long nep, ap;
            PACK2(nep, ne, ne);
            PACK2(ap, ea.y, ea.y);
            #pragma unroll
            for (int pi = 0; pi < 4; pi++) {
                float2 w2 = swp[i*32 + pi*8 + g];
                unsigned long long wp, alpha, beta;
                PACK2(wp, w2.x, w2.y);
                FMA2(alpha, nep, wp, onep);
                MUL2(beta, wp, ap);
                MUL2(A[pi], A[pi], alpha);
                FMA2(Bv[pi], alpha, Bv[pi], beta);
            }
        }
        if (team == 1) {
            #pragma unroll
            for (int pi = 0; pi < 4; pi++) {
                float lo, hi;
                UNPACK2(lo, hi, A[pi]);
                pubA1[pi*256 + ttid] = make_float2(lo, hi);
                UNPACK2(lo, hi, Bv[pi]);
                pubB1[pi*256 + ttid] = make_float2(lo, hi);
            }
        } else if (team == 2) {
            #pragma unroll
            for (int pi = 0; pi < 4; pi++) {
                float lo, hi;
                UNPACK2(lo, hi, A[pi]);
                pubA2[pi*256 + ttid] = make_float2(lo, hi);
                UNPACK2(lo, hi, Bv[pi]);
                pubB2[pi*256 + ttid] = make_float2(lo, hi);
            }
        }
    }
    __syncthreads();

    if (team > 0) {
        unsigned long long mvp[4];
        #pragma unroll
        for (int pi = 0; pi < 4; pi++) {
            float2 v = pubMv[pi*256 + ttid];
            PACK2(mvp[pi], v.x, v.y);
        }
        if (team >= 2) {
            #pragma unroll
            for (int pi = 0; pi < 4; pi++) {
                float2 Av = pubA1[pi*256 + ttid];
                float2 Bv = pubB1[pi*256 + ttid];
                unsigned long long Ap, Bp;
                PACK2(Ap, Av.x, Av.y);
                PACK2(Bp, Bv.x, Bv.y);
                FMA2(mvp[pi], Ap, mvp[pi], Bp);
            }
        }
        if (team == 3) {
            #pragma unroll
            for (int pi = 0; pi < 4; pi++) {
                float2 Av = pubA2[pi*256 + ttid];
                float2 Bv = pubB2[pi*256 + ttid];
                unsigned long long Ap, Bp;
                PACK2(Ap, Av.x, Av.y);
                PACK2(Bp, Bv.x, Bv.y);
                FMA2(mvp[pi], Ap, mvp[pi], Bp);
            }
        }
        float* outr = g_read + b*LL*DD + team*CT*DD + dbase + dl;
        scan_reads(swT, seaT, mvp, outr, g, dl);
    }
}

// ============================================================
// Kernel C: output MLP. 64 positions/block, grid=200, block=256.
// Warp handles 8 positions; lane owns d-cols (lane, lane+32).
// ============================================================
__global__ __launch_bounds__(256) void output_kernel(
    const int*  __restrict__ cseqs, const int* __restrict__ shc,
    const float* __restrict__ Wf,   const float* __restrict__ Wp,
    const float* __restrict__ bp,   float* __restrict__ out)
{
    __shared__ float sW[DD*DD];
    __shared__ float rs[64][DD];

    const int tid   = threadIdx.x;
    const int lane  = tid & 31;
    const int warp  = tid >> 5;
    const int pbase = blockIdx.x * 64;

    #pragma unroll
    for (int j = tid; j < DD*DD/4; j += 256)
        ((float4*)sW)[j] = ((const float4*)Wf)[j];
    #pragma unroll
    for (int j = tid; j < 64*DD/4; j += 256)
        ((float4*)rs)[j] = ((const float4*)(g_read + pbase*DD))[j];
    __syncthreads();

    float acc0[8], acc1[8];
    int posq[8];
    #pragma unroll
    for (int jj = 0; jj < 8; jj++) {
        int pos = pbase + warp*8 + jj;
        int bb = pos / LL, t = pos - bb*LL;
        int q = (t == 0) ? cseqs[bb*L1S] : shc[bb*L1S + t - 1];
        posq[jj] = pos;
        acc0[jj] = g_Kf[q*DD + lane];
        acc1[jj] = g_Kf[q*DD + 32 + lane];
    }

    #pragma unroll
    for (int i4 = 0; i4 < DD/4; i4++) {
        float4 rv[8];
        #pragma unroll
        for (int jj = 0; jj < 8; jj++)
            rv[jj] = ((const float4*)rs[warp*8 + jj])[i4];
        #pragma unroll
        for (int k = 0; k < 4; k++) {
            const float wv0 = sW[(4*i4 + k)*DD + lane];
            const float wv1 = sW[(4*i4 + k)*DD + 32 + lane];
            #pragma unroll
            for (int jj = 0; jj < 8; jj++) {
                const float r = ((const float*)&rv[jj])[k];
                acc0[jj] = fmaf(r, wv0, acc0[jj]);
                acc1[jj] = fmaf(r, wv1, acc1[jj]);
            }
        }
    }

    const float wp0 = Wp[lane];
    const float wp1 = Wp[32 + lane];
    const float bpv = bp[0];
    #pragma unroll
    for (int jj = 0; jj < 8; jj++) {
        float p = fast_tanh(acc0[jj]) * wp0 + fast_tanh(acc1[jj]) * wp1;
        #pragma unroll
        for (int o = 16; o > 0; o >>= 1)
            p += __shfl_xor_sync(0xffffffffu, p, o);
        if (lane == 0)
            out[posq[jj]] = fast_sigmoid(p + bpv);
    }
}

// ============================================================
extern "C" void kernel_launch(void* const* d_in, const int* in_sizes, int n_in,
                              void* d_out, int out_size)
{
    const int*   cseqs = (const int*)  d_in[0];
    const int*   rseqs = (const int*)  d_in[1];
    const int*   shc   = (const int*)  d_in[2];
    const int*   shr   = (const int*)  d_in[3];
    const float* kemb  = (const float*)d_in[4];
    const float* vemb  = (const float*)d_in[5];
    const float* Mk    = (const float*)d_in[6];
    const float* Mv0   = (const float*)d_in[7];
    const float* Wf    = (const float*)d_in[8];
    const float* bf    = (const float*)d_in[9];
    const float* We    = (const float*)d_in[10];
    const float* be    = (const float*)d_in[11];
    const float* Wa    = (const float*)d_in[12];
    const float* ba    = (const float*)d_in[13];
    const float* Wp    = (const float*)d_in[14];
    const float* bp    = (const float*)d_in[15];
    float* out = (float*)d_out;

    size_t vsm = (size_t)(2*DD*DD + 16*DD + 32) * sizeof(float);
    cudaFuncSetAttribute(vocab_kernel,
                         cudaFuncAttributeMaxDynamicSharedMemorySize, (int)vsm);
    vocab_kernel<<<NEA + NWK, 256, vsm>>>(kemb, vemb, Mk, We, be, Wa, ba, Wf, bf);

    size_t ssm = (size_t)(8*CT*64 + 5*1024*2) * sizeof(float)
               + (size_t)(8*CT) * sizeof(int);
    cudaFuncSetAttribute(scan_fused,
                         cudaFuncAttributeMaxDynamicSharedMemorySize, (int)ssm);
    scan_fused<<<BB*2, 1024, ssm>>>(cseqs, rseqs, shc, shr, Mv0);

    output_kernel<<<BB*LL/64, 256>>>(cseqs, shc, Wf, Wp, bp, out);
}